// round 1
// baseline (speedup 1.0000x reference)
#include <cuda_runtime.h>
#include <math.h>

#define B_ 4
#define S_ 2048
#define D_ 1024
#define H_ 16
#define DH 64

// Scratch (allocation-free rule: device globals)
__device__ float g_q[B_*S_*H_*DH];
__device__ float g_k[B_*S_*H_*DH];
__device__ float g_v[B_*S_*H_*DH];
__device__ float g_x[B_*S_*H_*DH];

// ---------------------------------------------------------------------------
// SGEMM: C[M,N] = A[M,K] * B[K,N], all row-major. BM=BN=128, BK=8, 8x8/thread.
// ---------------------------------------------------------------------------
__global__ __launch_bounds__(256) void sgemm_kernel(
    const float* __restrict__ A, const float* __restrict__ Bm,
    float* __restrict__ C, int M, int N, int K)
{
    __shared__ float As[8][128];
    __shared__ float Bs[8][128];

    const int tid = threadIdx.x;
    const int tr = tid >> 4;          // 0..15
    const int tc = tid & 15;          // 0..15
    const int irA = tid >> 1;         // 0..127
    const int icA = (tid & 1) * 4;    // 0 or 4
    const int irB = tid >> 5;         // 0..7
    const int icB = (tid & 31) * 4;   // 0..124

    const float* Ab = A + (size_t)blockIdx.y * 128 * K;
    const float* Bb = Bm + blockIdx.x * 128;
    float* Cb = C + (size_t)blockIdx.y * 128 * N + blockIdx.x * 128;

    float acc[8][8];
    #pragma unroll
    for (int i = 0; i < 8; i++)
        #pragma unroll
        for (int j = 0; j < 8; j++) acc[i][j] = 0.f;

    float rM[8], rN[8];

    for (int k0 = 0; k0 < K; k0 += 8) {
        float4 a = *(const float4*)(Ab + (size_t)irA * K + icA);
        As[icA + 0][irA] = a.x;
        As[icA + 1][irA] = a.y;
        As[icA + 2][irA] = a.z;
        As[icA + 3][irA] = a.w;
        *(float4*)(&Bs[irB][icB]) = *(const float4*)(Bb + (size_t)irB * N + icB);
        __syncthreads();

        #pragma unroll
        for (int k = 0; k < 8; k++) {
            *(float4*)(rM)     = *(const float4*)(&As[k][tr * 8]);
            *(float4*)(rM + 4) = *(const float4*)(&As[k][tr * 8 + 4]);
            *(float4*)(rN)     = *(const float4*)(&Bs[k][tc * 8]);
            *(float4*)(rN + 4) = *(const float4*)(&Bs[k][tc * 8 + 4]);
            #pragma unroll
            for (int i = 0; i < 8; i++)
                #pragma unroll
                for (int j = 0; j < 8; j++)
                    acc[i][j] = fmaf(rM[i], rN[j], acc[i][j]);
        }
        __syncthreads();
        Ab += 8;
        Bb += (size_t)8 * N;
    }

    #pragma unroll
    for (int i = 0; i < 8; i++) {
        float* crow = Cb + (size_t)(tr * 8 + i) * N + tc * 8;
        *(float4*)(crow)     = make_float4(acc[i][0], acc[i][1], acc[i][2], acc[i][3]);
        *(float4*)(crow + 4) = make_float4(acc[i][4], acc[i][5], acc[i][6], acc[i][7]);
    }
}

// ---------------------------------------------------------------------------
// RoPE on q (with 1/sqrt(Dh) fold) and k, in place.
// One thread per (b,s,h,d) with d in [0,32).
// ---------------------------------------------------------------------------
__global__ __launch_bounds__(256) void rope_kernel(
    float* __restrict__ q, float* __restrict__ k, const int* __restrict__ segpos)
{
    const int idx = blockIdx.x * blockDim.x + threadIdx.x;   // 2^22 total
    const int d = idx & 31;
    const int rest = idx >> 5;            // (b*S+s)*H + h
    const int bs = rest >> 4;             // b*S+s

    const int p = segpos[bs];
    // angle = p / 10000^(d/32) = p * exp(-d * ln(10000)/32)
    const float ang = (float)p * expf(-(float)d * 0.28782313662425574f);
    float sv, cv;
    sincosf(ang, &sv, &cv);

    const size_t base = (size_t)rest * 64 + d;
    float q1 = q[base], q2 = q[base + 32];
    q[base]      = (q1 * cv - q2 * sv) * 0.125f;
    q[base + 32] = (q2 * cv + q1 * sv) * 0.125f;
    float k1 = k[base], k2 = k[base + 32];
    k[base]      = k1 * cv - k2 * sv;
    k[base + 32] = k2 * cv + k1 * sv;
}

// ---------------------------------------------------------------------------
// Flash-style causal attention: one CTA per (q-tile of 64, head, batch).
// 256 threads: row = tid/4 (q row in tile), quad = tid%4 owns 16 cols/dims.
// Smem (dynamic): Qs, Ks, Vs, Ps, each 64 rows x stride 68 floats.
// ---------------------------------------------------------------------------
#define FSTR 68
__global__ __launch_bounds__(256) void flash_kernel()
{
    extern __shared__ float sm[];
    float* Qs = sm;
    float* Ks = sm + 64 * FSTR;
    float* Vs = sm + 2 * 64 * FSTR;
    float* Ps = sm + 3 * 64 * FSTR;

    const int qt = blockIdx.x;    // q tile (0..31)
    const int h  = blockIdx.y;
    const int b  = blockIdx.z;
    const int tid = threadIdx.x;
    const int row  = tid >> 2;    // 0..63
    const int quad = tid & 3;     // 0..3
    const int c0 = quad * 16;
    const int q0 = qt * 64;

    // Load Q tile
    {
        const float* qg = g_q + (((size_t)(b * S_ + q0 + row)) * H_ + h) * DH + c0;
        float* qs = Qs + row * FSTR + c0;
        #pragma unroll
        for (int i = 0; i < 16; i += 4)
            *(float4*)(qs + i) = *(const float4*)(qg + i);
    }

    float o[16];
    #pragma unroll
    for (int j = 0; j < 16; j++) o[j] = 0.f;
    float m_prev = -INFINITY;
    float l = 0.f;

    for (int kt = 0; kt <= qt; kt++) {
        __syncthreads();   // previous iteration done reading Ks/Vs/Ps
        const int k0 = kt * 64;
        {
            const size_t goff = (((size_t)(b * S_ + k0 + row)) * H_ + h) * DH + c0;
            const float* kg = g_k + goff;
            const float* vg = g_v + goff;
            float* ks = Ks + row * FSTR + c0;
            float* vs = Vs + row * FSTR + c0;
            #pragma unroll
            for (int i = 0; i < 16; i += 4) {
                *(float4*)(ks + i) = *(const float4*)(kg + i);
                *(float4*)(vs + i) = *(const float4*)(vg + i);
            }
        }
        __syncthreads();

        // scores: s[c] = Q[row,:] . K[c0+c,:]
        float s[16];
        #pragma unroll
        for (int c = 0; c < 16; c++) s[c] = 0.f;
        const float* qrow = Qs + row * FSTR;
        #pragma unroll
        for (int d = 0; d < 64; d += 4) {
            float4 qv = *(const float4*)(qrow + d);
            #pragma unroll
            for (int c = 0; c < 16; c++) {
                float4 kv = *(const float4*)(Ks + (c0 + c) * FSTR + d);
                s[c] = fmaf(qv.x, kv.x, s[c]);
                s[c] = fmaf(qv.y, kv.y, s[c]);
                s[c] = fmaf(qv.z, kv.z, s[c]);
                s[c] = fmaf(qv.w, kv.w, s[c]);
            }
        }

        if (kt == qt) {
            #pragma unroll
            for (int c = 0; c < 16; c++)
                if (k0 + c0 + c > q0 + row) s[c] = -INFINITY;
        }

        // online softmax
        float mloc = s[0];
        #pragma unroll
        for (int c = 1; c < 16; c++) mloc = fmaxf(mloc, s[c]);
        mloc = fmaxf(mloc, __shfl_xor_sync(0xffffffffu, mloc, 1));
        mloc = fmaxf(mloc, __shfl_xor_sync(0xffffffffu, mloc, 2));
        const float m_new = fmaxf(m_prev, mloc);
        const float scale = expf(m_prev - m_new);   // 0 on first tile

        float lloc = 0.f;
        float* prow = Ps + row * FSTR + c0;
        #pragma unroll
        for (int c = 0; c < 16; c++) {
            float p = expf(s[c] - m_new);
            prow[c] = p;
            lloc += p;
        }
        lloc += __shfl_xor_sync(0xffffffffu, lloc, 1);
        lloc += __shfl_xor_sync(0xffffffffu, lloc, 2);
        l = l * scale + lloc;
        #pragma unroll
        for (int j = 0; j < 16; j++) o[j] *= scale;

        __syncthreads();   // Ps fully written

        // O += P @ V  (thread owns dims c0..c0+15 of its row)
        const float* pr = Ps + row * FSTR;
        #pragma unroll
        for (int k = 0; k < 64; k += 4) {
            float4 pv = *(const float4*)(pr + k);
            #pragma unroll
            for (int kk = 0; kk < 4; kk++) {
                float p = (kk == 0) ? pv.x : (kk == 1) ? pv.y : (kk == 2) ? pv.z : pv.w;
                const float* vr = Vs + (k + kk) * FSTR + c0;
                #pragma unroll
                for (int j = 0; j < 16; j += 4) {
                    float4 vv = *(const float4*)(vr + j);
                    o[j + 0] = fmaf(p, vv.x, o[j + 0]);
                    o[j + 1] = fmaf(p, vv.y, o[j + 1]);
                    o[j + 2] = fmaf(p, vv.z, o[j + 2]);
                    o[j + 3] = fmaf(p, vv.w, o[j + 3]);
                }
            }
        }
        m_prev = m_new;
    }

    const float inv = 1.f / l;
    float* xg = g_x + (((size_t)(b * S_ + q0 + row)) * H_ + h) * DH + c0;
    #pragma unroll
    for (int j = 0; j < 16; j += 4) {
        float4 ov;
        ov.x = o[j + 0] * inv;
        ov.y = o[j + 1] * inv;
        ov.z = o[j + 2] * inv;
        ov.w = o[j + 3] * inv;
        *(float4*)(xg + j) = ov;
    }
}

// ---------------------------------------------------------------------------
extern "C" void kernel_launch(void* const* d_in, const int* in_sizes, int n_in,
                              void* d_out, int out_size)
{
    (void)in_sizes; (void)n_in; (void)out_size;
    const float* inputs = (const float*)d_in[0];
    const float* w_q    = (const float*)d_in[1];
    const float* w_k    = (const float*)d_in[2];
    const float* w_v    = (const float*)d_in[3];
    const float* w_out  = (const float*)d_in[4];
    const int*   segpos = (const int*)d_in[5];
    // d_in[6] = mask: causal tril by construction; computed analytically.
    float* out = (float*)d_out;

    float *q, *k, *v, *x;
    cudaGetSymbolAddress((void**)&q, g_q);
    cudaGetSymbolAddress((void**)&k, g_k);
    cudaGetSymbolAddress((void**)&v, g_v);
    cudaGetSymbolAddress((void**)&x, g_x);

    const int M = B_ * S_;   // 8192
    dim3 gg(D_ / 128, M / 128);   // (8, 64)

    sgemm_kernel<<<gg, 256>>>(inputs, w_q, q, M, D_, D_);
    sgemm_kernel<<<gg, 256>>>(inputs, w_k, k, M, D_, D_);
    sgemm_kernel<<<gg, 256>>>(inputs, w_v, v, M, D_, D_);

    const int rope_threads = B_ * S_ * H_ * (DH / 2);   // 4194304
    rope_kernel<<<rope_threads / 256, 256>>>(q, k, segpos);

    const int fsmem = 4 * 64 * FSTR * (int)sizeof(float);   // 69632
    cudaFuncSetAttribute(flash_kernel, cudaFuncAttributeMaxDynamicSharedMemorySize, fsmem);
    flash_kernel<<<dim3(S_ / 64, H_, B_), 256, fsmem>>>();

    sgemm_kernel<<<gg, 256>>>(x, w_out, out, M, D_, D_);
}

// round 2
// speedup vs baseline: 1.1504x; 1.1504x over previous
#include <cuda_runtime.h>
#include <math.h>
#include <stdint.h>

#define B_ 4
#define S_ 2048
#define D_ 1024
#define H_ 16
#define DH 64

// Scratch (allocation-free rule: device globals)
__device__ float g_q[B_*S_*H_*DH];
__device__ float g_k[B_*S_*H_*DH];
__device__ float g_v[B_*S_*H_*DH];
__device__ float g_x[B_*S_*H_*DH];

__device__ __forceinline__ uint32_t f2tf32(float f) {
    uint32_t u;
    asm("cvt.rna.tf32.f32 %0, %1;" : "=r"(u) : "f"(f));
    return u;
}

// ---------------------------------------------------------------------------
// TF32 tensor-core GEMM: C[M,N] = A[M,K]*B[K,N], row-major fp32 in/out.
// BM=BN=128, BK=16. 256 threads = 8 warps (4 x 2), warp tile 32x64.
// mma.sync.aligned.m16n8k8.row.col.f32.tf32.tf32.f32
// ---------------------------------------------------------------------------
#define BM 128
#define BN 128
#define BK 16
#define PADW 136   // 128 + 8 words: fragment LDS bank = (8*k + m) % 32, conflict-free

__global__ __launch_bounds__(256) void gemm_tf32(
    const float* __restrict__ A, const float* __restrict__ Bm,
    float* __restrict__ C, int M, int N, int K)
{
    __shared__ uint32_t As[2][BK][PADW];   // k-major: As[k][m]
    __shared__ uint32_t Bs[2][BK][PADW];   // k-major: Bs[k][n]

    const int tid  = threadIdx.x;
    const int warp = tid >> 5;
    const int lane = tid & 31;
    const int gid  = lane >> 2;   // 0..7
    const int tig  = lane & 3;    // 0..3
    const int wm   = warp >> 1;   // 0..3
    const int wn   = warp & 1;    // 0..1

    const int m0 = blockIdx.y * BM;
    const int n0 = blockIdx.x * BN;

    // global tile load mapping
    const int arow = tid >> 1;           // 0..127
    const int acol = (tid & 1) * 8;      // 0 or 8
    const int brow = tid >> 4;           // 0..15
    const int bcol = (tid & 15) * 8;     // 0..120

    const float* Ag = A + (size_t)(m0 + arow) * K + acol;
    const float* Bg = Bm + (size_t)brow * N + n0 + bcol;

    float c[2][8][4];
    #pragma unroll
    for (int mt = 0; mt < 2; mt++)
        #pragma unroll
        for (int nt = 0; nt < 8; nt++)
            #pragma unroll
            for (int r = 0; r < 4; r++) c[mt][nt][r] = 0.f;

    float pa[8], pb[8];

    // prefetch tile 0 and stage into buffer 0
    *(float4*)(pa)     = *(const float4*)(Ag);
    *(float4*)(pa + 4) = *(const float4*)(Ag + 4);
    *(float4*)(pb)     = *(const float4*)(Bg);
    *(float4*)(pb + 4) = *(const float4*)(Bg + 4);
    #pragma unroll
    for (int j = 0; j < 8; j++) As[0][acol + j][arow] = f2tf32(pa[j]);
    #pragma unroll
    for (int j = 0; j < 8; j++) Bs[0][brow][bcol + j] = f2tf32(pb[j]);
    __syncthreads();

    const int niter = K / BK;
    for (int it = 0; it < niter; it++) {
        const int cur = it & 1;

        if (it + 1 < niter) {
            const float* Ag2 = Ag + (it + 1) * BK;
            const float* Bg2 = Bg + (size_t)(it + 1) * BK * N;
            *(float4*)(pa)     = *(const float4*)(Ag2);
            *(float4*)(pa + 4) = *(const float4*)(Ag2 + 4);
            *(float4*)(pb)     = *(const float4*)(Bg2);
            *(float4*)(pb + 4) = *(const float4*)(Bg2 + 4);
        }

        #pragma unroll
        for (int ks = 0; ks < 2; ks++) {
            const int kb = ks * 8;
            uint32_t afr[2][4];
            #pragma unroll
            for (int mt = 0; mt < 2; mt++) {
                const int rb = wm * 32 + mt * 16 + gid;
                afr[mt][0] = As[cur][kb + tig][rb];
                afr[mt][1] = As[cur][kb + tig][rb + 8];
                afr[mt][2] = As[cur][kb + tig + 4][rb];
                afr[mt][3] = As[cur][kb + tig + 4][rb + 8];
            }
            uint32_t bfr[8][2];
            #pragma unroll
            for (int nt = 0; nt < 8; nt++) {
                const int cb = wn * 64 + nt * 8 + gid;
                bfr[nt][0] = Bs[cur][kb + tig][cb];
                bfr[nt][1] = Bs[cur][kb + tig + 4][cb];
            }
            #pragma unroll
            for (int mt = 0; mt < 2; mt++)
                #pragma unroll
                for (int nt = 0; nt < 8; nt++) {
                    asm volatile(
                        "mma.sync.aligned.m16n8k8.row.col.f32.tf32.tf32.f32 "
                        "{%0,%1,%2,%3}, {%4,%5,%6,%7}, {%8,%9}, {%0,%1,%2,%3};"
                        : "+f"(c[mt][nt][0]), "+f"(c[mt][nt][1]),
                          "+f"(c[mt][nt][2]), "+f"(c[mt][nt][3])
                        : "r"(afr[mt][0]), "r"(afr[mt][1]),
                          "r"(afr[mt][2]), "r"(afr[mt][3]),
                          "r"(bfr[nt][0]), "r"(bfr[nt][1]));
                }
        }

        if (it + 1 < niter) {
            const int nxt = cur ^ 1;
            #pragma unroll
            for (int j = 0; j < 8; j++) As[nxt][acol + j][arow] = f2tf32(pa[j]);
            #pragma unroll
            for (int j = 0; j < 8; j++) Bs[nxt][brow][bcol + j] = f2tf32(pb[j]);
        }
        __syncthreads();
    }

    // writeback
    #pragma unroll
    for (int mt = 0; mt < 2; mt++) {
        const int r = m0 + wm * 32 + mt * 16 + gid;
        #pragma unroll
        for (int nt = 0; nt < 8; nt++) {
            const int cc = n0 + wn * 64 + nt * 8 + tig * 2;
            *(float2*)(C + (size_t)r * N + cc)       = make_float2(c[mt][nt][0], c[mt][nt][1]);
            *(float2*)(C + (size_t)(r + 8) * N + cc) = make_float2(c[mt][nt][2], c[mt][nt][3]);
        }
    }
}

// ---------------------------------------------------------------------------
// RoPE on q (with 1/sqrt(Dh) fold) and k, in place.
// ---------------------------------------------------------------------------
__global__ __launch_bounds__(256) void rope_kernel(
    float* __restrict__ q, float* __restrict__ k, const int* __restrict__ segpos)
{
    const int idx = blockIdx.x * blockDim.x + threadIdx.x;
    const int d = idx & 31;
    const int rest = idx >> 5;
    const int bs = rest >> 4;

    const int p = segpos[bs];
    const float ang = (float)p * expf(-(float)d * 0.28782313662425574f);
    float sv, cv;
    sincosf(ang, &sv, &cv);

    const size_t base = (size_t)rest * 64 + d;
    float q1 = q[base], q2 = q[base + 32];
    q[base]      = (q1 * cv - q2 * sv) * 0.125f;
    q[base + 32] = (q2 * cv + q1 * sv) * 0.125f;
    float k1 = k[base], k2 = k[base + 32];
    k[base]      = k1 * cv - k2 * sv;
    k[base + 32] = k2 * cv + k1 * sv;
}

// ---------------------------------------------------------------------------
// Flash-style causal attention (fp32), unchanged from R1.
// ---------------------------------------------------------------------------
#define FSTR 68
__global__ __launch_bounds__(256) void flash_kernel()
{
    extern __shared__ float sm[];
    float* Qs = sm;
    float* Ks = sm + 64 * FSTR;
    float* Vs = sm + 2 * 64 * FSTR;
    float* Ps = sm + 3 * 64 * FSTR;

    const int qt = blockIdx.x;
    const int h  = blockIdx.y;
    const int b  = blockIdx.z;
    const int tid = threadIdx.x;
    const int row  = tid >> 2;
    const int quad = tid & 3;
    const int c0 = quad * 16;
    const int q0 = qt * 64;

    {
        const float* qg = g_q + (((size_t)(b * S_ + q0 + row)) * H_ + h) * DH + c0;
        float* qs = Qs + row * FSTR + c0;
        #pragma unroll
        for (int i = 0; i < 16; i += 4)
            *(float4*)(qs + i) = *(const float4*)(qg + i);
    }

    float o[16];
    #pragma unroll
    for (int j = 0; j < 16; j++) o[j] = 0.f;
    float m_prev = -INFINITY;
    float l = 0.f;

    for (int kt = 0; kt <= qt; kt++) {
        __syncthreads();
        const int k0 = kt * 64;
        {
            const size_t goff = (((size_t)(b * S_ + k0 + row)) * H_ + h) * DH + c0;
            const float* kg = g_k + goff;
            const float* vg = g_v + goff;
            float* ks = Ks + row * FSTR + c0;
            float* vs = Vs + row * FSTR + c0;
            #pragma unroll
            for (int i = 0; i < 16; i += 4) {
                *(float4*)(ks + i) = *(const float4*)(kg + i);
                *(float4*)(vs + i) = *(const float4*)(vg + i);
            }
        }
        __syncthreads();

        float s[16];
        #pragma unroll
        for (int c = 0; c < 16; c++) s[c] = 0.f;
        const float* qrow = Qs + row * FSTR;
        #pragma unroll
        for (int d = 0; d < 64; d += 4) {
            float4 qv = *(const float4*)(qrow + d);
            #pragma unroll
            for (int c = 0; c < 16; c++) {
                float4 kv = *(const float4*)(Ks + (c0 + c) * FSTR + d);
                s[c] = fmaf(qv.x, kv.x, s[c]);
                s[c] = fmaf(qv.y, kv.y, s[c]);
                s[c] = fmaf(qv.z, kv.z, s[c]);
                s[c] = fmaf(qv.w, kv.w, s[c]);
            }
        }

        if (kt == qt) {
            #pragma unroll
            for (int c = 0; c < 16; c++)
                if (k0 + c0 + c > q0 + row) s[c] = -INFINITY;
        }

        float mloc = s[0];
        #pragma unroll
        for (int c = 1; c < 16; c++) mloc = fmaxf(mloc, s[c]);
        mloc = fmaxf(mloc, __shfl_xor_sync(0xffffffffu, mloc, 1));
        mloc = fmaxf(mloc, __shfl_xor_sync(0xffffffffu, mloc, 2));
        const float m_new = fmaxf(m_prev, mloc);
        const float scale = expf(m_prev - m_new);

        float lloc = 0.f;
        float* prow = Ps + row * FSTR + c0;
        #pragma unroll
        for (int c = 0; c < 16; c++) {
            float p = expf(s[c] - m_new);
            prow[c] = p;
            lloc += p;
        }
        lloc += __shfl_xor_sync(0xffffffffu, lloc, 1);
        lloc += __shfl_xor_sync(0xffffffffu, lloc, 2);
        l = l * scale + lloc;
        #pragma unroll
        for (int j = 0; j < 16; j++) o[j] *= scale;

        __syncthreads();

        const float* pr = Ps + row * FSTR;
        #pragma unroll
        for (int k = 0; k < 64; k += 4) {
            float4 pv = *(const float4*)(pr + k);
            #pragma unroll
            for (int kk = 0; kk < 4; kk++) {
                float p = (kk == 0) ? pv.x : (kk == 1) ? pv.y : (kk == 2) ? pv.z : pv.w;
                const float* vr = Vs + (k + kk) * FSTR + c0;
                #pragma unroll
                for (int j = 0; j < 16; j += 4) {
                    float4 vv = *(const float4*)(vr + j);
                    o[j + 0] = fmaf(p, vv.x, o[j + 0]);
                    o[j + 1] = fmaf(p, vv.y, o[j + 1]);
                    o[j + 2] = fmaf(p, vv.z, o[j + 2]);
                    o[j + 3] = fmaf(p, vv.w, o[j + 3]);
                }
            }
        }
        m_prev = m_new;
    }

    const float inv = 1.f / l;
    float* xg = g_x + (((size_t)(b * S_ + q0 + row)) * H_ + h) * DH + c0;
    #pragma unroll
    for (int j = 0; j < 16; j += 4) {
        float4 ov;
        ov.x = o[j + 0] * inv;
        ov.y = o[j + 1] * inv;
        ov.z = o[j + 2] * inv;
        ov.w = o[j + 3] * inv;
        *(float4*)(xg + j) = ov;
    }
}

// ---------------------------------------------------------------------------
extern "C" void kernel_launch(void* const* d_in, const int* in_sizes, int n_in,
                              void* d_out, int out_size)
{
    (void)in_sizes; (void)n_in; (void)out_size;
    const float* inputs = (const float*)d_in[0];
    const float* w_q    = (const float*)d_in[1];
    const float* w_k    = (const float*)d_in[2];
    const float* w_v    = (const float*)d_in[3];
    const float* w_out  = (const float*)d_in[4];
    const int*   segpos = (const int*)d_in[5];
    float* out = (float*)d_out;

    float *q, *k, *v, *x;
    cudaGetSymbolAddress((void**)&q, g_q);
    cudaGetSymbolAddress((void**)&k, g_k);
    cudaGetSymbolAddress((void**)&v, g_v);
    cudaGetSymbolAddress((void**)&x, g_x);

    const int M = B_ * S_;   // 8192
    dim3 gg(D_ / BN, M / BM);   // (8, 64)

    gemm_tf32<<<gg, 256>>>(inputs, w_q, q, M, D_, D_);
    gemm_tf32<<<gg, 256>>>(inputs, w_k, k, M, D_, D_);
    gemm_tf32<<<gg, 256>>>(inputs, w_v, v, M, D_, D_);

    const int rope_threads = B_ * S_ * H_ * (DH / 2);
    rope_kernel<<<rope_threads / 256, 256>>>(q, k, segpos);

    const int fsmem = 4 * 64 * FSTR * (int)sizeof(float);
    cudaFuncSetAttribute(flash_kernel, cudaFuncAttributeMaxDynamicSharedMemorySize, fsmem);
    flash_kernel<<<dim3(S_ / 64, H_, B_), 256, fsmem>>>();

    gemm_tf32<<<gg, 256>>>(x, w_out, out, M, D_, D_);
}

// round 3
// speedup vs baseline: 6.8756x; 5.9767x over previous
#include <cuda_runtime.h>
#include <math.h>
#include <stdint.h>

#define B_ 4
#define S_ 2048
#define D_ 1024
#define H_ 16
#define DH 64

__device__ float g_q[B_*S_*H_*DH];
__device__ float g_k[B_*S_*H_*DH];
__device__ float g_v[B_*S_*H_*DH];
__device__ float g_x[B_*S_*H_*DH];

__device__ __forceinline__ uint32_t f2tf32(float f) {
    uint32_t u;
    asm("cvt.rna.tf32.f32 %0, %1;" : "=r"(u) : "f"(f));
    return u;
}

#define MMA_TF32(c0,c1,c2,c3,a0,a1,a2,a3,b0,b1)                          \
    asm volatile(                                                        \
        "mma.sync.aligned.m16n8k8.row.col.f32.tf32.tf32.f32 "            \
        "{%0,%1,%2,%3}, {%4,%5,%6,%7}, {%8,%9}, {%0,%1,%2,%3};"          \
        : "+f"(c0), "+f"(c1), "+f"(c2), "+f"(c3)                         \
        : "r"(a0), "r"(a1), "r"(a2), "r"(a3), "r"(b0), "r"(b1))

// ---------------------------------------------------------------------------
// TF32 tensor-core GEMM (unchanged from R2).
// ---------------------------------------------------------------------------
#define BM 128
#define BN 128
#define BK 16
#define PADW 136

__global__ __launch_bounds__(256) void gemm_tf32(
    const float* __restrict__ A, const float* __restrict__ Bm,
    float* __restrict__ C, int M, int N, int K)
{
    __shared__ uint32_t As[2][BK][PADW];
    __shared__ uint32_t Bs[2][BK][PADW];

    const int tid  = threadIdx.x;
    const int warp = tid >> 5;
    const int lane = tid & 31;
    const int gid  = lane >> 2;
    const int tig  = lane & 3;
    const int wm   = warp >> 1;
    const int wn   = warp & 1;

    const int m0 = blockIdx.y * BM;
    const int n0 = blockIdx.x * BN;

    const int arow = tid >> 1;
    const int acol = (tid & 1) * 8;
    const int brow = tid >> 4;
    const int bcol = (tid & 15) * 8;

    const float* Ag = A + (size_t)(m0 + arow) * K + acol;
    const float* Bg = Bm + (size_t)brow * N + n0 + bcol;

    float c[2][8][4];
    #pragma unroll
    for (int mt = 0; mt < 2; mt++)
        #pragma unroll
        for (int nt = 0; nt < 8; nt++)
            #pragma unroll
            for (int r = 0; r < 4; r++) c[mt][nt][r] = 0.f;

    float pa[8], pb[8];

    *(float4*)(pa)     = *(const float4*)(Ag);
    *(float4*)(pa + 4) = *(const float4*)(Ag + 4);
    *(float4*)(pb)     = *(const float4*)(Bg);
    *(float4*)(pb + 4) = *(const float4*)(Bg + 4);
    #pragma unroll
    for (int j = 0; j < 8; j++) As[0][acol + j][arow] = f2tf32(pa[j]);
    #pragma unroll
    for (int j = 0; j < 8; j++) Bs[0][brow][bcol + j] = f2tf32(pb[j]);
    __syncthreads();

    const int niter = K / BK;
    for (int it = 0; it < niter; it++) {
        const int cur = it & 1;

        if (it + 1 < niter) {
            const float* Ag2 = Ag + (it + 1) * BK;
            const float* Bg2 = Bg + (size_t)(it + 1) * BK * N;
            *(float4*)(pa)     = *(const float4*)(Ag2);
            *(float4*)(pa + 4) = *(const float4*)(Ag2 + 4);
            *(float4*)(pb)     = *(const float4*)(Bg2);
            *(float4*)(pb + 4) = *(const float4*)(Bg2 + 4);
        }

        #pragma unroll
        for (int ks = 0; ks < 2; ks++) {
            const int kb = ks * 8;
            uint32_t afr[2][4];
            #pragma unroll
            for (int mt = 0; mt < 2; mt++) {
                const int rb = wm * 32 + mt * 16 + gid;
                afr[mt][0] = As[cur][kb + tig][rb];
                afr[mt][1] = As[cur][kb + tig][rb + 8];
                afr[mt][2] = As[cur][kb + tig + 4][rb];
                afr[mt][3] = As[cur][kb + tig + 4][rb + 8];
            }
            uint32_t bfr[8][2];
            #pragma unroll
            for (int nt = 0; nt < 8; nt++) {
                const int cb = wn * 64 + nt * 8 + gid;
                bfr[nt][0] = Bs[cur][kb + tig][cb];
                bfr[nt][1] = Bs[cur][kb + tig + 4][cb];
            }
            #pragma unroll
            for (int mt = 0; mt < 2; mt++)
                #pragma unroll
                for (int nt = 0; nt < 8; nt++)
                    MMA_TF32(c[mt][nt][0], c[mt][nt][1], c[mt][nt][2], c[mt][nt][3],
                             afr[mt][0], afr[mt][1], afr[mt][2], afr[mt][3],
                             bfr[nt][0], bfr[nt][1]);
        }

        if (it + 1 < niter) {
            const int nxt = cur ^ 1;
            #pragma unroll
            for (int j = 0; j < 8; j++) As[nxt][acol + j][arow] = f2tf32(pa[j]);
            #pragma unroll
            for (int j = 0; j < 8; j++) Bs[nxt][brow][bcol + j] = f2tf32(pb[j]);
        }
        __syncthreads();
    }

    #pragma unroll
    for (int mt = 0; mt < 2; mt++) {
        const int r = m0 + wm * 32 + mt * 16 + gid;
        #pragma unroll
        for (int nt = 0; nt < 8; nt++) {
            const int cc = n0 + wn * 64 + nt * 8 + tig * 2;
            *(float2*)(C + (size_t)r * N + cc)       = make_float2(c[mt][nt][0], c[mt][nt][1]);
            *(float2*)(C + (size_t)(r + 8) * N + cc) = make_float2(c[mt][nt][2], c[mt][nt][3]);
        }
    }
}

// ---------------------------------------------------------------------------
// RoPE (unchanged).
// ---------------------------------------------------------------------------
__global__ __launch_bounds__(256) void rope_kernel(
    float* __restrict__ q, float* __restrict__ k, const int* __restrict__ segpos)
{
    const int idx = blockIdx.x * blockDim.x + threadIdx.x;
    const int d = idx & 31;
    const int rest = idx >> 5;
    const int bs = rest >> 4;

    const int p = segpos[bs];
    const float ang = (float)p * expf(-(float)d * 0.28782313662425574f);
    float sv, cv;
    sincosf(ang, &sv, &cv);

    const size_t base = (size_t)rest * 64 + d;
    float q1 = q[base], q2 = q[base + 32];
    q[base]      = (q1 * cv - q2 * sv) * 0.125f;
    q[base + 32] = (q2 * cv + q1 * sv) * 0.125f;
    float k1 = k[base], k2 = k[base + 32];
    k[base]      = k1 * cv - k2 * sv;
    k[base + 32] = k2 * cv + k1 * sv;
}

// ---------------------------------------------------------------------------
// Tensor-core flash attention (tf32 mma).
// CTA: 128 q-rows x one (b,h). 8 warps, warp tile M=16, N=64(kv)/64(dim).
// k-tiles of 64; causal; online softmax in mma accumulator layout.
// ---------------------------------------------------------------------------
#define BQ   128
#define KSTR 72   // ≡8 (mod 32): conflict-free b-fragment LDS
#define PSTR 68   // ≡4 (mod 32): conflict-free a-fragment LDS
#define QWORDS (BQ * PSTR)          // 8704
#define KWORDS (64 * KSTR)          // 4608
#define FTC_SMEM_WORDS (QWORDS + 2 * KWORDS + 8 * 16 * PSTR)

__global__ __launch_bounds__(256) void flash_tc()
{
    extern __shared__ uint32_t sm[];
    uint32_t* Qs = sm;                              // [qrow][dim]  stride PSTR
    uint32_t* Ks = sm + QWORDS;                     // [dim][kcol]  stride KSTR
    uint32_t* Vs = sm + QWORDS + KWORDS;            // [kcol][dim]  stride KSTR
    uint32_t* Pw = sm + QWORDS + 2 * KWORDS;        // per-warp [16][PSTR]

    const int qt = blockIdx.x;
    const int h  = blockIdx.y;
    const int b  = blockIdx.z;
    const int tid  = threadIdx.x;
    const int warp = tid >> 5;
    const int lane = tid & 31;
    const int g = lane >> 2;          // 0..7
    const int t = lane & 3;           // 0..3
    const int q0 = qt * BQ;
    const int wrow0 = warp * 16;      // warp's local row base
    uint32_t* Ps = Pw + warp * 16 * PSTR;

    // stage Q (tf32) once: thread -> row tid/2, half (tid&1)*32
    {
        const int qr = tid >> 1;
        const int dc = (tid & 1) * 32;
        const float* qg = g_q + (((size_t)(b * S_ + q0 + qr)) * H_ + h) * DH + dc;
        #pragma unroll
        for (int j = 0; j < 32; j += 4) {
            float4 v4 = *(const float4*)(qg + j);
            Qs[qr * PSTR + dc + j]     = f2tf32(v4.x);
            Qs[qr * PSTR + dc + j + 1] = f2tf32(v4.y);
            Qs[qr * PSTR + dc + j + 2] = f2tf32(v4.z);
            Qs[qr * PSTR + dc + j + 3] = f2tf32(v4.w);
        }
    }

    float o[8][4];
    #pragma unroll
    for (int nt = 0; nt < 8; nt++)
        #pragma unroll
        for (int r = 0; r < 4; r++) o[nt][r] = 0.f;
    float m0r = -INFINITY, m1r = -INFINITY, l0 = 0.f, l1 = 0.f;

    // K/V tile load mapping: thread -> kcol tid&63, quarter tid>>6
    const int kc = tid & 63;
    const int dq = (tid >> 6) * 16;

    const int nkt = 2 * qt + 2;
    for (int kt = 0; kt < nkt; kt++) {
        const int k0 = kt * 64;

        // prefetch K/V from gmem (no smem touch yet)
        float4 kr[4], vr[4];
        {
            const size_t goff = (((size_t)(b * S_ + k0 + kc)) * H_ + h) * DH + dq;
            const float* kg = g_k + goff;
            const float* vg = g_v + goff;
            #pragma unroll
            for (int j = 0; j < 4; j++) {
                kr[j] = *(const float4*)(kg + j * 4);
                vr[j] = *(const float4*)(vg + j * 4);
            }
        }
        __syncthreads();   // previous iteration done reading Ks/Vs
        // K transposed: Ks[dim][kcol]
        #pragma unroll
        for (int j = 0; j < 4; j++) {
            Ks[(dq + j * 4 + 0) * KSTR + kc] = f2tf32(kr[j].x);
            Ks[(dq + j * 4 + 1) * KSTR + kc] = f2tf32(kr[j].y);
            Ks[(dq + j * 4 + 2) * KSTR + kc] = f2tf32(kr[j].z);
            Ks[(dq + j * 4 + 3) * KSTR + kc] = f2tf32(kr[j].w);
        }
        // V natural: Vs[kcol][dim]
        #pragma unroll
        for (int j = 0; j < 4; j++) {
            uint4 u;
            u.x = f2tf32(vr[j].x); u.y = f2tf32(vr[j].y);
            u.z = f2tf32(vr[j].z); u.w = f2tf32(vr[j].w);
            *(uint4*)&Vs[kc * KSTR + dq + j * 4] = u;
        }
        __syncthreads();

        // S = Q @ K^T : warp tile 16 x 64
        float s[8][4];
        #pragma unroll
        for (int nt = 0; nt < 8; nt++)
            #pragma unroll
            for (int r = 0; r < 4; r++) s[nt][r] = 0.f;

        #pragma unroll
        for (int ks = 0; ks < 8; ks++) {
            const int kb = ks * 8;
            uint32_t a0 = Qs[(wrow0 + g) * PSTR + kb + t];
            uint32_t a1 = Qs[(wrow0 + g + 8) * PSTR + kb + t];
            uint32_t a2 = Qs[(wrow0 + g) * PSTR + kb + t + 4];
            uint32_t a3 = Qs[(wrow0 + g + 8) * PSTR + kb + t + 4];
            #pragma unroll
            for (int nt = 0; nt < 8; nt++) {
                uint32_t b0 = Ks[(kb + t) * KSTR + nt * 8 + g];
                uint32_t b1 = Ks[(kb + t + 4) * KSTR + nt * 8 + g];
                MMA_TF32(s[nt][0], s[nt][1], s[nt][2], s[nt][3],
                         a0, a1, a2, a3, b0, b1);
            }
        }

        // causal mask (only the two diagonal-straddling tiles need it)
        if (kt >= 2 * qt) {
            const int row0 = q0 + wrow0 + g;
            #pragma unroll
            for (int nt = 0; nt < 8; nt++) {
                const int col = k0 + nt * 8 + 2 * t;
                if (col     > row0)     s[nt][0] = -INFINITY;
                if (col + 1 > row0)     s[nt][1] = -INFINITY;
                if (col     > row0 + 8) s[nt][2] = -INFINITY;
                if (col + 1 > row0 + 8) s[nt][3] = -INFINITY;
            }
        }

        // online softmax (rows g and g+8)
        float mx0 = -INFINITY, mx1 = -INFINITY;
        #pragma unroll
        for (int nt = 0; nt < 8; nt++) {
            mx0 = fmaxf(mx0, fmaxf(s[nt][0], s[nt][1]));
            mx1 = fmaxf(mx1, fmaxf(s[nt][2], s[nt][3]));
        }
        mx0 = fmaxf(mx0, __shfl_xor_sync(0xffffffffu, mx0, 1));
        mx0 = fmaxf(mx0, __shfl_xor_sync(0xffffffffu, mx0, 2));
        mx1 = fmaxf(mx1, __shfl_xor_sync(0xffffffffu, mx1, 1));
        mx1 = fmaxf(mx1, __shfl_xor_sync(0xffffffffu, mx1, 2));

        const float mn0 = fmaxf(m0r, mx0);
        const float mn1 = fmaxf(m1r, mx1);
        const float sc0 = __expf(m0r - mn0);
        const float sc1 = __expf(m1r - mn1);

        float ls0 = 0.f, ls1 = 0.f;
        #pragma unroll
        for (int nt = 0; nt < 8; nt++) {
            float p0 = __expf(s[nt][0] - mn0);
            float p1 = __expf(s[nt][1] - mn0);
            float p2 = __expf(s[nt][2] - mn1);
            float p3 = __expf(s[nt][3] - mn1);
            ls0 += p0 + p1;
            ls1 += p2 + p3;
            uint2 u01 = make_uint2(f2tf32(p0), f2tf32(p1));
            uint2 u23 = make_uint2(f2tf32(p2), f2tf32(p3));
            *(uint2*)&Ps[g * PSTR + nt * 8 + 2 * t]       = u01;
            *(uint2*)&Ps[(g + 8) * PSTR + nt * 8 + 2 * t] = u23;
        }
        ls0 += __shfl_xor_sync(0xffffffffu, ls0, 1);
        ls0 += __shfl_xor_sync(0xffffffffu, ls0, 2);
        ls1 += __shfl_xor_sync(0xffffffffu, ls1, 1);
        ls1 += __shfl_xor_sync(0xffffffffu, ls1, 2);
        l0 = l0 * sc0 + ls0;
        l1 = l1 * sc1 + ls1;
        #pragma unroll
        for (int nt = 0; nt < 8; nt++) {
            o[nt][0] *= sc0; o[nt][1] *= sc0;
            o[nt][2] *= sc1; o[nt][3] *= sc1;
        }
        m0r = mn0; m1r = mn1;

        __syncwarp();   // Ps visible within warp

        // O += P @ V
        #pragma unroll
        for (int ks = 0; ks < 8; ks++) {
            const int kb = ks * 8;
            uint32_t a0 = Ps[g * PSTR + kb + t];
            uint32_t a1 = Ps[(g + 8) * PSTR + kb + t];
            uint32_t a2 = Ps[g * PSTR + kb + t + 4];
            uint32_t a3 = Ps[(g + 8) * PSTR + kb + t + 4];
            #pragma unroll
            for (int nt = 0; nt < 8; nt++) {
                uint32_t b0 = Vs[(kb + t) * KSTR + nt * 8 + g];
                uint32_t b1 = Vs[(kb + t + 4) * KSTR + nt * 8 + g];
                MMA_TF32(o[nt][0], o[nt][1], o[nt][2], o[nt][3],
                         a0, a1, a2, a3, b0, b1);
            }
        }
        __syncwarp();   // done reading Ps before next overwrite
    }

    // writeback
    const float i0 = 1.f / l0;
    const float i1 = 1.f / l1;
    float* xg0 = g_x + (((size_t)(b * S_ + q0 + wrow0 + g)) * H_ + h) * DH;
    float* xg1 = xg0 + (size_t)8 * H_ * DH;
    #pragma unroll
    for (int nt = 0; nt < 8; nt++) {
        *(float2*)(xg0 + nt * 8 + 2 * t) = make_float2(o[nt][0] * i0, o[nt][1] * i0);
        *(float2*)(xg1 + nt * 8 + 2 * t) = make_float2(o[nt][2] * i1, o[nt][3] * i1);
    }
}

// ---------------------------------------------------------------------------
extern "C" void kernel_launch(void* const* d_in, const int* in_sizes, int n_in,
                              void* d_out, int out_size)
{
    (void)in_sizes; (void)n_in; (void)out_size;
    const float* inputs = (const float*)d_in[0];
    const float* w_q    = (const float*)d_in[1];
    const float* w_k    = (const float*)d_in[2];
    const float* w_v    = (const float*)d_in[3];
    const float* w_out  = (const float*)d_in[4];
    const int*   segpos = (const int*)d_in[5];
    float* out = (float*)d_out;

    float *q, *k, *v, *x;
    cudaGetSymbolAddress((void**)&q, g_q);
    cudaGetSymbolAddress((void**)&k, g_k);
    cudaGetSymbolAddress((void**)&v, g_v);
    cudaGetSymbolAddress((void**)&x, g_x);

    const int M = B_ * S_;
    dim3 gg(D_ / BN, M / BM);

    gemm_tf32<<<gg, 256>>>(inputs, w_q, q, M, D_, D_);
    gemm_tf32<<<gg, 256>>>(inputs, w_k, k, M, D_, D_);
    gemm_tf32<<<gg, 256>>>(inputs, w_v, v, M, D_, D_);

    const int rope_threads = B_ * S_ * H_ * (DH / 2);
    rope_kernel<<<rope_threads / 256, 256>>>(q, k, segpos);

    const int fsmem = FTC_SMEM_WORDS * (int)sizeof(uint32_t);
    cudaFuncSetAttribute(flash_tc, cudaFuncAttributeMaxDynamicSharedMemorySize, fsmem);
    flash_tc<<<dim3(S_ / BQ, H_, B_), 256, fsmem>>>();

    gemm_tf32<<<gg, 256>>>(x, w_out, out, M, D_, D_);
}

// round 5
// speedup vs baseline: 7.5296x; 1.0951x over previous
#include <cuda_runtime.h>
#include <math.h>
#include <stdint.h>

#define B_ 4
#define S_ 2048
#define D_ 1024
#define H_ 16
#define DH 64

__device__ float g_q[B_*S_*H_*DH];
__device__ float g_k[B_*S_*H_*DH];
__device__ float g_v[B_*S_*H_*DH];
__device__ float g_x[B_*S_*H_*DH];
__device__ float g_a[B_*S_*D_];        // tf32-rounded inputs
__device__ float g_wt[4*1024*1024];    // transposed + tf32-rounded weights

__device__ __forceinline__ uint32_t f2tf32(float f) {
    uint32_t u;
    asm("cvt.rna.tf32.f32 %0, %1;" : "=r"(u) : "f"(f));
    return u;
}

__device__ __forceinline__ uint32_t smem_u32(const void* p) {
    uint32_t a;
    asm("{ .reg .u64 t; cvta.to.shared.u64 t, %1; cvt.u32.u64 %0, t; }" : "=r"(a) : "l"(p));
    return a;
}

#define MMA_TF32(c0,c1,c2,c3,a0,a1,a2,a3,b0,b1)                          \
    asm volatile(                                                        \
        "mma.sync.aligned.m16n8k8.row.col.f32.tf32.tf32.f32 "            \
        "{%0,%1,%2,%3}, {%4,%5,%6,%7}, {%8,%9}, {%0,%1,%2,%3};"          \
        : "+f"(c0), "+f"(c1), "+f"(c2), "+f"(c3)                         \
        : "r"(a0), "r"(a1), "r"(a2), "r"(a3), "r"(b0), "r"(b1))

#define CP16(dst, src) asm volatile("cp.async.cg.shared.global [%0], [%1], 16;" :: "r"(dst), "l"(src))
#define CP_COMMIT()    asm volatile("cp.async.commit_group;" ::: "memory")
#define CP_WAIT2()     asm volatile("cp.async.wait_group 2;" ::: "memory")

// ---------------------------------------------------------------------------
// Prep: tf32-round inputs.
// ---------------------------------------------------------------------------
__global__ __launch_bounds__(256) void round_inputs(
    const float* __restrict__ src, float* __restrict__ dst)
{
    const int i = blockIdx.x * blockDim.x + threadIdx.x;
    float4 v = *(const float4*)(src + (size_t)i * 4);
    uint4 u;
    u.x = f2tf32(v.x); u.y = f2tf32(v.y); u.z = f2tf32(v.z); u.w = f2tf32(v.w);
    *(uint4*)(dst + (size_t)i * 4) = u;
}

// ---------------------------------------------------------------------------
// Weight transpose + tf32 round: wt[n][k] = round(W[k][n]) for 4 weights.
// ---------------------------------------------------------------------------
__global__ __launch_bounds__(256) void transpose_round(
    const float* __restrict__ w0, const float* __restrict__ w1,
    const float* __restrict__ w2, const float* __restrict__ w3,
    float* __restrict__ dst)
{
    __shared__ float tile[32][33];
    const int z = blockIdx.z;
    const float* src = (z == 0) ? w0 : (z == 1) ? w1 : (z == 2) ? w2 : w3;
    float* out = dst + (size_t)z * 1024 * 1024;
    const int n0 = blockIdx.x * 32;
    const int k0 = blockIdx.y * 32;
    const int tx = threadIdx.x;
    const int ty = threadIdx.y;

    #pragma unroll
    for (int j = 0; j < 4; j++)
        tile[ty + j * 8][tx] = src[(size_t)(k0 + ty + j * 8) * 1024 + n0 + tx];
    __syncthreads();
    #pragma unroll
    for (int j = 0; j < 4; j++) {
        uint32_t r = f2tf32(tile[tx][ty + j * 8]);
        out[(size_t)(n0 + ty + j * 8) * 1024 + k0 + tx] = __uint_as_float(r);
    }
}

// ---------------------------------------------------------------------------
// Pipelined tf32 mma GEMM. C[8192, N] = A[8192,1024] @ Bt[N,1024]^T.
// BM=BN=128, BK=16, 4-stage cp.async. Operands pre-rounded to tf32.
// Epilogue routes by n-block (Q/K/V fusion); for single output pass same ptr.
// Smem rows: 20 words stride (80B, 16B-aligned, conflict-free frags).
// ---------------------------------------------------------------------------
#define GSTR 20
#define STG_WORDS (128 * GSTR)   // 2560 words = 10240 B per stage
#define GSMEM_BYTES (8 * STG_WORDS * 4)   // 4 A stages + 4 B stages = 80 KB

__global__ __launch_bounds__(256) void gemm_tc(
    const float* __restrict__ A, const float* __restrict__ Bt,
    float* __restrict__ Cq, float* __restrict__ Ck, float* __restrict__ Cv)
{
    extern __shared__ uint32_t smw[];
    const uint32_t sbase = smem_u32(smw);

    const int tid  = threadIdx.x;
    const int warp = tid >> 5;
    const int lane = tid & 31;
    const int g = lane >> 2;
    const int t = lane & 3;
    const int wm = warp >> 1;   // 0..3
    const int wn = warp & 1;    // 0..1

    const int m0 = blockIdx.y * 128;
    const int n0 = blockIdx.x * 128;
    const int sel  = n0 >> 10;
    const int col0 = n0 & 1023;
    float* C = (sel == 0) ? Cq : (sel == 1) ? Ck : Cv;

    // load mapping: row = tid/2 (for A-m and B-n), two 16B chunks each
    const int lrow = tid >> 1;
    const int koff = (tid & 1) * 8;          // float offset of first chunk
    const float* ag = A  + (size_t)(m0 + lrow) * 1024 + koff;
    const float* bg = Bt + (size_t)(n0 + lrow) * 1024 + koff;
    const uint32_t adst = sbase + (uint32_t)(lrow * 80 + koff * 4);
    const uint32_t bdst = adst + 4 * STG_WORDS * 4;

    float c[2][8][4];
    #pragma unroll
    for (int mt = 0; mt < 2; mt++)
        #pragma unroll
        for (int nt = 0; nt < 8; nt++)
            #pragma unroll
            for (int r = 0; r < 4; r++) c[mt][nt][r] = 0.f;

    // prologue: issue stages 0..2
    #pragma unroll
    for (int s = 0; s < 3; s++) {
        const float* a = ag + s * 16;
        const float* b = bg + s * 16;
        CP16(adst + s * 10240,      a);
        CP16(adst + s * 10240 + 16, a + 4);
        CP16(bdst + s * 10240,      b);
        CP16(bdst + s * 10240 + 16, b + 4);
        CP_COMMIT();
    }

    const int ab_w[4] = { 0, STG_WORDS, 2 * STG_WORDS, 3 * STG_WORDS };

    for (int kt = 0; kt < 64; kt++) {
        CP_WAIT2();
        __syncthreads();

        // issue stage kt+3
        if (kt + 3 < 64) {
            const int s = (kt + 3) & 3;
            const float* a = ag + (kt + 3) * 16;
            const float* b = bg + (kt + 3) * 16;
            CP16(adst + s * 10240,      a);
            CP16(adst + s * 10240 + 16, a + 4);
            CP16(bdst + s * 10240,      b);
            CP16(bdst + s * 10240 + 16, b + 4);
        }
        CP_COMMIT();

        const int buf = kt & 3;
        const uint32_t* As = smw + ab_w[buf];
        const uint32_t* Bs = smw + 4 * STG_WORDS + ab_w[buf];

        #pragma unroll
        for (int ks = 0; ks < 2; ks++) {
            const int kb = ks * 8;
            uint32_t afr[2][4];
            #pragma unroll
            for (int mt = 0; mt < 2; mt++) {
                const int rb = wm * 32 + mt * 16 + g;
                afr[mt][0] = As[rb * GSTR + kb + t];
                afr[mt][1] = As[(rb + 8) * GSTR + kb + t];
                afr[mt][2] = As[rb * GSTR + kb + t + 4];
                afr[mt][3] = As[(rb + 8) * GSTR + kb + t + 4];
            }
            uint32_t bfr[8][2];
            #pragma unroll
            for (int nt = 0; nt < 8; nt++) {
                const int cb = wn * 64 + nt * 8 + g;
                bfr[nt][0] = Bs[cb * GSTR + kb + t];
                bfr[nt][1] = Bs[cb * GSTR + kb + t + 4];
            }
            #pragma unroll
            for (int mt = 0; mt < 2; mt++)
                #pragma unroll
                for (int nt = 0; nt < 8; nt++)
                    MMA_TF32(c[mt][nt][0], c[mt][nt][1], c[mt][nt][2], c[mt][nt][3],
                             afr[mt][0], afr[mt][1], afr[mt][2], afr[mt][3],
                             bfr[nt][0], bfr[nt][1]);
        }
    }

    #pragma unroll
    for (int mt = 0; mt < 2; mt++) {
        const int r = m0 + wm * 32 + mt * 16 + g;
        #pragma unroll
        for (int nt = 0; nt < 8; nt++) {
            const int cc = col0 + wn * 64 + nt * 8 + t * 2;
            *(float2*)(C + (size_t)r * 1024 + cc)       = make_float2(c[mt][nt][0], c[mt][nt][1]);
            *(float2*)(C + (size_t)(r + 8) * 1024 + cc) = make_float2(c[mt][nt][2], c[mt][nt][3]);
        }
    }
}

// ---------------------------------------------------------------------------
// RoPE (unchanged).
// ---------------------------------------------------------------------------
__global__ __launch_bounds__(256) void rope_kernel(
    float* __restrict__ q, float* __restrict__ k, const int* __restrict__ segpos)
{
    const int idx = blockIdx.x * blockDim.x + threadIdx.x;
    const int d = idx & 31;
    const int rest = idx >> 5;
    const int bs = rest >> 4;

    const int p = segpos[bs];
    const float ang = (float)p * expf(-(float)d * 0.28782313662425574f);
    float sv, cv;
    sincosf(ang, &sv, &cv);

    const size_t base = (size_t)rest * 64 + d;
    float q1 = q[base], q2 = q[base + 32];
    q[base]      = (q1 * cv - q2 * sv) * 0.125f;
    q[base + 32] = (q2 * cv + q1 * sv) * 0.125f;
    float k1 = k[base], k2 = k[base + 32];
    k[base]      = k1 * cv - k2 * sv;
    k[base + 32] = k2 * cv + k1 * sv;
}

// ---------------------------------------------------------------------------
// Legacy-mma tf32 flash attention (R3) — epilogue now stores tf32-rounded x.
// ---------------------------------------------------------------------------
#define BQ   128
#define KSTR 72
#define PSTR 68
#define QWORDS (BQ * PSTR)
#define KWORDS (64 * KSTR)
#define FTC_SMEM_WORDS (QWORDS + 2 * KWORDS + 8 * 16 * PSTR)

__global__ __launch_bounds__(256) void flash_tc()
{
    extern __shared__ uint32_t sm[];
    uint32_t* Qs = sm;
    uint32_t* Ks = sm + QWORDS;
    uint32_t* Vs = sm + QWORDS + KWORDS;
    uint32_t* Pw = sm + QWORDS + 2 * KWORDS;

    const int qt = blockIdx.x;
    const int h  = blockIdx.y;
    const int b  = blockIdx.z;
    const int tid  = threadIdx.x;
    const int warp = tid >> 5;
    const int lane = tid & 31;
    const int g = lane >> 2;
    const int t = lane & 3;
    const int q0 = qt * BQ;
    const int wrow0 = warp * 16;
    uint32_t* Ps = Pw + warp * 16 * PSTR;

    {
        const int qr = tid >> 1;
        const int dc = (tid & 1) * 32;
        const float* qg = g_q + (((size_t)(b * S_ + q0 + qr)) * H_ + h) * DH + dc;
        #pragma unroll
        for (int j = 0; j < 32; j += 4) {
            float4 v4 = *(const float4*)(qg + j);
            Qs[qr * PSTR + dc + j]     = f2tf32(v4.x);
            Qs[qr * PSTR + dc + j + 1] = f2tf32(v4.y);
            Qs[qr * PSTR + dc + j + 2] = f2tf32(v4.z);
            Qs[qr * PSTR + dc + j + 3] = f2tf32(v4.w);
        }
    }

    float o[8][4];
    #pragma unroll
    for (int nt = 0; nt < 8; nt++)
        #pragma unroll
        for (int r = 0; r < 4; r++) o[nt][r] = 0.f;
    float m0r = -INFINITY, m1r = -INFINITY, l0 = 0.f, l1 = 0.f;

    const int kc = tid & 63;
    const int dq = (tid >> 6) * 16;

    const int nkt = 2 * qt + 2;
    for (int kt = 0; kt < nkt; kt++) {
        const int k0 = kt * 64;

        float4 kr[4], vr[4];
        {
            const size_t goff = (((size_t)(b * S_ + k0 + kc)) * H_ + h) * DH + dq;
            const float* kg = g_k + goff;
            const float* vg = g_v + goff;
            #pragma unroll
            for (int j = 0; j < 4; j++) {
                kr[j] = *(const float4*)(kg + j * 4);
                vr[j] = *(const float4*)(vg + j * 4);
            }
        }
        __syncthreads();
        #pragma unroll
        for (int j = 0; j < 4; j++) {
            Ks[(dq + j * 4 + 0) * KSTR + kc] = f2tf32(kr[j].x);
            Ks[(dq + j * 4 + 1) * KSTR + kc] = f2tf32(kr[j].y);
            Ks[(dq + j * 4 + 2) * KSTR + kc] = f2tf32(kr[j].z);
            Ks[(dq + j * 4 + 3) * KSTR + kc] = f2tf32(kr[j].w);
        }
        #pragma unroll
        for (int j = 0; j < 4; j++) {
            uint4 u;
            u.x = f2tf32(vr[j].x); u.y = f2tf32(vr[j].y);
            u.z = f2tf32(vr[j].z); u.w = f2tf32(vr[j].w);
            *(uint4*)&Vs[kc * KSTR + dq + j * 4] = u;
        }
        __syncthreads();

        float s[8][4];
        #pragma unroll
        for (int nt = 0; nt < 8; nt++)
            #pragma unroll
            for (int r = 0; r < 4; r++) s[nt][r] = 0.f;

        #pragma unroll
        for (int ks = 0; ks < 8; ks++) {
            const int kb = ks * 8;
            uint32_t a0 = Qs[(wrow0 + g) * PSTR + kb + t];
            uint32_t a1 = Qs[(wrow0 + g + 8) * PSTR + kb + t];
            uint32_t a2 = Qs[(wrow0 + g) * PSTR + kb + t + 4];
            uint32_t a3 = Qs[(wrow0 + g + 8) * PSTR + kb + t + 4];
            #pragma unroll
            for (int nt = 0; nt < 8; nt++) {
                uint32_t b0 = Ks[(kb + t) * KSTR + nt * 8 + g];
                uint32_t b1 = Ks[(kb + t + 4) * KSTR + nt * 8 + g];
                MMA_TF32(s[nt][0], s[nt][1], s[nt][2], s[nt][3],
                         a0, a1, a2, a3, b0, b1);
            }
        }

        if (kt >= 2 * qt) {
            const int row0 = q0 + wrow0 + g;
            #pragma unroll
            for (int nt = 0; nt < 8; nt++) {
                const int col = k0 + nt * 8 + 2 * t;
                if (col     > row0)     s[nt][0] = -INFINITY;
                if (col + 1 > row0)     s[nt][1] = -INFINITY;
                if (col     > row0 + 8) s[nt][2] = -INFINITY;
                if (col + 1 > row0 + 8) s[nt][3] = -INFINITY;
            }
        }

        float mx0 = -INFINITY, mx1 = -INFINITY;
        #pragma unroll
        for (int nt = 0; nt < 8; nt++) {
            mx0 = fmaxf(mx0, fmaxf(s[nt][0], s[nt][1]));
            mx1 = fmaxf(mx1, fmaxf(s[nt][2], s[nt][3]));
        }
        mx0 = fmaxf(mx0, __shfl_xor_sync(0xffffffffu, mx0, 1));
        mx0 = fmaxf(mx0, __shfl_xor_sync(0xffffffffu, mx0, 2));
        mx1 = fmaxf(mx1, __shfl_xor_sync(0xffffffffu, mx1, 1));
        mx1 = fmaxf(mx1, __shfl_xor_sync(0xffffffffu, mx1, 2));

        const float mn0 = fmaxf(m0r, mx0);
        const float mn1 = fmaxf(m1r, mx1);
        const float sc0 = __expf(m0r - mn0);
        const float sc1 = __expf(m1r - mn1);

        float ls0 = 0.f, ls1 = 0.f;
        #pragma unroll
        for (int nt = 0; nt < 8; nt++) {
            float p0 = __expf(s[nt][0] - mn0);
            float p1 = __expf(s[nt][1] - mn0);
            float p2 = __expf(s[nt][2] - mn1);
            float p3 = __expf(s[nt][3] - mn1);
            ls0 += p0 + p1;
            ls1 += p2 + p3;
            uint2 u01 = make_uint2(f2tf32(p0), f2tf32(p1));
            uint2 u23 = make_uint2(f2tf32(p2), f2tf32(p3));
            *(uint2*)&Ps[g * PSTR + nt * 8 + 2 * t]       = u01;
            *(uint2*)&Ps[(g + 8) * PSTR + nt * 8 + 2 * t] = u23;
        }
        ls0 += __shfl_xor_sync(0xffffffffu, ls0, 1);
        ls0 += __shfl_xor_sync(0xffffffffu, ls0, 2);
        ls1 += __shfl_xor_sync(0xffffffffu, ls1, 1);
        ls1 += __shfl_xor_sync(0xffffffffu, ls1, 2);
        l0 = l0 * sc0 + ls0;
        l1 = l1 * sc1 + ls1;
        #pragma unroll
        for (int nt = 0; nt < 8; nt++) {
            o[nt][0] *= sc0; o[nt][1] *= sc0;
            o[nt][2] *= sc1; o[nt][3] *= sc1;
        }
        m0r = mn0; m1r = mn1;

        __syncwarp();

        #pragma unroll
        for (int ks = 0; ks < 8; ks++) {
            const int kb = ks * 8;
            uint32_t a0 = Ps[g * PSTR + kb + t];
            uint32_t a1 = Ps[(g + 8) * PSTR + kb + t];
            uint32_t a2 = Ps[g * PSTR + kb + t + 4];
            uint32_t a3 = Ps[(g + 8) * PSTR + kb + t + 4];
            #pragma unroll
            for (int nt = 0; nt < 8; nt++) {
                uint32_t b0 = Vs[(kb + t) * KSTR + nt * 8 + g];
                uint32_t b1 = Vs[(kb + t + 4) * KSTR + nt * 8 + g];
                MMA_TF32(o[nt][0], o[nt][1], o[nt][2], o[nt][3],
                         a0, a1, a2, a3, b0, b1);
            }
        }
        __syncwarp();
    }

    // writeback: tf32-rounded (consumed as mma A operand by out-proj GEMM)
    const float i0 = 1.f / l0;
    const float i1 = 1.f / l1;
    float* xg0 = g_x + (((size_t)(b * S_ + q0 + wrow0 + g)) * H_ + h) * DH;
    float* xg1 = xg0 + (size_t)8 * H_ * DH;
    #pragma unroll
    for (int nt = 0; nt < 8; nt++) {
        uint2 u0 = make_uint2(f2tf32(o[nt][0] * i0), f2tf32(o[nt][1] * i0));
        uint2 u1 = make_uint2(f2tf32(o[nt][2] * i1), f2tf32(o[nt][3] * i1));
        *(uint2*)(xg0 + nt * 8 + 2 * t) = u0;
        *(uint2*)(xg1 + nt * 8 + 2 * t) = u1;
    }
}

// ---------------------------------------------------------------------------
extern "C" void kernel_launch(void* const* d_in, const int* in_sizes, int n_in,
                              void* d_out, int out_size)
{
    (void)in_sizes; (void)n_in; (void)out_size;
    const float* inputs = (const float*)d_in[0];
    const float* w_q    = (const float*)d_in[1];
    const float* w_k    = (const float*)d_in[2];
    const float* w_v    = (const float*)d_in[3];
    const float* w_out  = (const float*)d_in[4];
    const int*   segpos = (const int*)d_in[5];
    float* out = (float*)d_out;

    float *q, *k, *v, *x, *a, *wt;
    cudaGetSymbolAddress((void**)&q, g_q);
    cudaGetSymbolAddress((void**)&k, g_k);
    cudaGetSymbolAddress((void**)&v, g_v);
    cudaGetSymbolAddress((void**)&x, g_x);
    cudaGetSymbolAddress((void**)&a, g_a);
    cudaGetSymbolAddress((void**)&wt, g_wt);

    round_inputs<<<B_ * S_ * D_ / 1024, 256>>>(inputs, a);
    transpose_round<<<dim3(32, 32, 4), dim3(32, 8)>>>(w_q, w_k, w_v, w_out, wt);

    cudaFuncSetAttribute(gemm_tc, cudaFuncAttributeMaxDynamicSharedMemorySize, GSMEM_BYTES);
    // fused QKV: N = 3072
    gemm_tc<<<dim3(24, 64), 256, GSMEM_BYTES>>>(a, wt, q, k, v);

    const int rope_threads = B_ * S_ * H_ * (DH / 2);
    rope_kernel<<<rope_threads / 256, 256>>>(q, k, segpos);

    const int fsmem = FTC_SMEM_WORDS * (int)sizeof(uint32_t);
    cudaFuncSetAttribute(flash_tc, cudaFuncAttributeMaxDynamicSharedMemorySize, fsmem);
    flash_tc<<<dim3(S_ / BQ, H_, B_), 256, fsmem>>>();

    // out-projection: N = 1024
    gemm_tc<<<dim3(8, 64), 256, GSMEM_BYTES>>>(x, wt + 3 * 1024 * 1024, out, out, out);
}

// round 6
// speedup vs baseline: 10.0156x; 1.3302x over previous
#include <cuda_runtime.h>
#include <cuda_fp16.h>
#include <math.h>
#include <stdint.h>

#define B_ 4
#define S_ 2048
#define D_ 1024
#define H_ 16
#define DH 64

__device__ float  g_q[B_*S_*H_*DH];
__device__ float  g_k[B_*S_*H_*DH];
__device__ float  g_v[B_*S_*H_*DH];
__device__ __half g_xh[B_*S_*H_*DH];     // flash output, fp16 (A of out-proj)
__device__ __half g_ah[B_*S_*D_];        // fp16 inputs
__device__ __half g_wth[4*1024*1024];    // transposed fp16 weights

__device__ __forceinline__ uint32_t f2tf32(float f) {
    uint32_t u;
    asm("cvt.rna.tf32.f32 %0, %1;" : "=r"(u) : "f"(f));
    return u;
}

__device__ __forceinline__ uint32_t smem_u32(const void* p) {
    uint32_t a;
    asm("{ .reg .u64 t; cvta.to.shared.u64 t, %1; cvt.u32.u64 %0, t; }" : "=r"(a) : "l"(p));
    return a;
}

#define MMA_TF32(c0,c1,c2,c3,a0,a1,a2,a3,b0,b1)                          \
    asm volatile(                                                        \
        "mma.sync.aligned.m16n8k8.row.col.f32.tf32.tf32.f32 "            \
        "{%0,%1,%2,%3}, {%4,%5,%6,%7}, {%8,%9}, {%0,%1,%2,%3};"          \
        : "+f"(c0), "+f"(c1), "+f"(c2), "+f"(c3)                         \
        : "r"(a0), "r"(a1), "r"(a2), "r"(a3), "r"(b0), "r"(b1))

#define MMA_F16(c0,c1,c2,c3,a0,a1,a2,a3,b0,b1)                           \
    asm volatile(                                                        \
        "mma.sync.aligned.m16n8k16.row.col.f32.f16.f16.f32 "             \
        "{%0,%1,%2,%3}, {%4,%5,%6,%7}, {%8,%9}, {%0,%1,%2,%3};"          \
        : "+f"(c0), "+f"(c1), "+f"(c2), "+f"(c3)                         \
        : "r"(a0), "r"(a1), "r"(a2), "r"(a3), "r"(b0), "r"(b1))

#define CP16(dst, src) asm volatile("cp.async.cg.shared.global [%0], [%1], 16;" :: "r"(dst), "l"(src))
#define CP_COMMIT()    asm volatile("cp.async.commit_group;" ::: "memory")
#define CP_WAIT2()     asm volatile("cp.async.wait_group 2;" ::: "memory")

// ---------------------------------------------------------------------------
// Prep: fp32 -> fp16 inputs (8 elems/thread).
// ---------------------------------------------------------------------------
__global__ __launch_bounds__(256) void to_half(
    const float* __restrict__ src, __half* __restrict__ dst)
{
    const size_t i = (size_t)(blockIdx.x * blockDim.x + threadIdx.x) * 8;
    float4 v0 = *(const float4*)(src + i);
    float4 v1 = *(const float4*)(src + i + 4);
    __half2 h[4];
    h[0] = __floats2half2_rn(v0.x, v0.y);
    h[1] = __floats2half2_rn(v0.z, v0.w);
    h[2] = __floats2half2_rn(v1.x, v1.y);
    h[3] = __floats2half2_rn(v1.z, v1.w);
    *(uint4*)(dst + i) = *(uint4*)h;
}

// ---------------------------------------------------------------------------
// Weight transpose + fp16: wt[n][k] = h(W[k][n]) for 4 weights.
// ---------------------------------------------------------------------------
__global__ __launch_bounds__(256) void transpose_half(
    const float* __restrict__ w0, const float* __restrict__ w1,
    const float* __restrict__ w2, const float* __restrict__ w3,
    __half* __restrict__ dst)
{
    __shared__ float tile[32][33];
    const int z = blockIdx.z;
    const float* src = (z == 0) ? w0 : (z == 1) ? w1 : (z == 2) ? w2 : w3;
    __half* out = dst + (size_t)z * 1024 * 1024;
    const int n0 = blockIdx.x * 32;
    const int k0 = blockIdx.y * 32;
    const int tx = threadIdx.x;
    const int ty = threadIdx.y;

    #pragma unroll
    for (int j = 0; j < 4; j++)
        tile[ty + j * 8][tx] = src[(size_t)(k0 + ty + j * 8) * 1024 + n0 + tx];
    __syncthreads();
    #pragma unroll
    for (int j = 0; j < 4; j++)
        out[(size_t)(n0 + ty + j * 8) * 1024 + k0 + tx] = __float2half(tile[tx][ty + j * 8]);
}

// ---------------------------------------------------------------------------
// fp16 mma GEMM. C[8192, N] = A[8192,1024] @ Bt[N,1024]^T, fp32 accum/output.
// BM=BN=128, BK=16 halves, 4-stage cp.async. Row stride 12 words (48 B).
// ---------------------------------------------------------------------------
#define GSTR 12
#define STG_WORDS (128 * GSTR)                 // 1536 words = 6144 B per stage
#define GSMEM_BYTES (8 * STG_WORDS * 4)        // 4 A + 4 B stages = 48 KB

__global__ __launch_bounds__(256) void gemm_h(
    const __half* __restrict__ A, const __half* __restrict__ Bt,
    float* __restrict__ Cq, float* __restrict__ Ck, float* __restrict__ Cv)
{
    extern __shared__ uint32_t smw[];
    const uint32_t sbase = smem_u32(smw);

    const int tid  = threadIdx.x;
    const int warp = tid >> 5;
    const int lane = tid & 31;
    const int g = lane >> 2;
    const int t = lane & 3;
    const int wm = warp >> 1;   // 0..3
    const int wn = warp & 1;    // 0..1

    const int m0 = blockIdx.y * 128;
    const int n0 = blockIdx.x * 128;
    const int sel  = n0 >> 10;
    const int col0 = n0 & 1023;
    float* C = (sel == 0) ? Cq : (sel == 1) ? Ck : Cv;

    // load mapping: row = tid/2, chunk = tid&1 (two 16B chunks per 32B row)
    const int lrow  = tid >> 1;
    const int chunk = tid & 1;
    const __half* ag = A  + (size_t)(m0 + lrow) * 1024 + chunk * 8;
    const __half* bg = Bt + (size_t)(n0 + lrow) * 1024 + chunk * 8;
    const uint32_t adst = sbase + (uint32_t)(lrow * 48 + chunk * 16);
    const uint32_t bdst = adst + 4 * STG_WORDS * 4;

    float c[2][8][4];
    #pragma unroll
    for (int mt = 0; mt < 2; mt++)
        #pragma unroll
        for (int nt = 0; nt < 8; nt++)
            #pragma unroll
            for (int r = 0; r < 4; r++) c[mt][nt][r] = 0.f;

    // prologue: stages 0..2
    #pragma unroll
    for (int s = 0; s < 3; s++) {
        CP16(adst + s * 6144, ag + s * 16);
        CP16(bdst + s * 6144, bg + s * 16);
        CP_COMMIT();
    }

    for (int kt = 0; kt < 64; kt++) {
        CP_WAIT2();
        __syncthreads();

        if (kt + 3 < 64) {
            const int s = (kt + 3) & 3;
            CP16(adst + s * 6144, ag + (kt + 3) * 16);
            CP16(bdst + s * 6144, bg + (kt + 3) * 16);
        }
        CP_COMMIT();

        const int buf = kt & 3;
        const uint32_t* As = smw + buf * STG_WORDS;
        const uint32_t* Bs = smw + 4 * STG_WORDS + buf * STG_WORDS;

        uint32_t afr[2][4];
        #pragma unroll
        for (int mt = 0; mt < 2; mt++) {
            const int rb = wm * 32 + mt * 16 + g;
            afr[mt][0] = As[rb * GSTR + t];
            afr[mt][1] = As[(rb + 8) * GSTR + t];
            afr[mt][2] = As[rb * GSTR + t + 4];
            afr[mt][3] = As[(rb + 8) * GSTR + t + 4];
        }
        uint32_t bfr[8][2];
        #pragma unroll
        for (int nt = 0; nt < 8; nt++) {
            const int cb = wn * 64 + nt * 8 + g;
            bfr[nt][0] = Bs[cb * GSTR + t];
            bfr[nt][1] = Bs[cb * GSTR + t + 4];
        }
        #pragma unroll
        for (int mt = 0; mt < 2; mt++)
            #pragma unroll
            for (int nt = 0; nt < 8; nt++)
                MMA_F16(c[mt][nt][0], c[mt][nt][1], c[mt][nt][2], c[mt][nt][3],
                        afr[mt][0], afr[mt][1], afr[mt][2], afr[mt][3],
                        bfr[nt][0], bfr[nt][1]);
    }

    #pragma unroll
    for (int mt = 0; mt < 2; mt++) {
        const int r = m0 + wm * 32 + mt * 16 + g;
        #pragma unroll
        for (int nt = 0; nt < 8; nt++) {
            const int cc = col0 + wn * 64 + nt * 8 + t * 2;
            *(float2*)(C + (size_t)r * 1024 + cc)       = make_float2(c[mt][nt][0], c[mt][nt][1]);
            *(float2*)(C + (size_t)(r + 8) * 1024 + cc) = make_float2(c[mt][nt][2], c[mt][nt][3]);
        }
    }
}

// ---------------------------------------------------------------------------
// RoPE (unchanged).
// ---------------------------------------------------------------------------
__global__ __launch_bounds__(256) void rope_kernel(
    float* __restrict__ q, float* __restrict__ k, const int* __restrict__ segpos)
{
    const int idx = blockIdx.x * blockDim.x + threadIdx.x;
    const int d = idx & 31;
    const int rest = idx >> 5;
    const int bs = rest >> 4;

    const int p = segpos[bs];
    const float ang = (float)p * expf(-(float)d * 0.28782313662425574f);
    float sv, cv;
    sincosf(ang, &sv, &cv);

    const size_t base = (size_t)rest * 64 + d;
    float q1 = q[base], q2 = q[base + 32];
    q[base]      = (q1 * cv - q2 * sv) * 0.125f;
    q[base + 32] = (q2 * cv + q1 * sv) * 0.125f;
    float k1 = k[base], k2 = k[base + 32];
    k[base]      = k1 * cv - k2 * sv;
    k[base + 32] = k2 * cv + k1 * sv;
}

// ---------------------------------------------------------------------------
// Legacy-mma tf32 flash attention — epilogue stores fp16 x.
// ---------------------------------------------------------------------------
#define BQ   128
#define KSTR 72
#define PSTR 68
#define QWORDS (BQ * PSTR)
#define KWORDS (64 * KSTR)
#define FTC_SMEM_WORDS (QWORDS + 2 * KWORDS + 8 * 16 * PSTR)

__global__ __launch_bounds__(256) void flash_tc()
{
    extern __shared__ uint32_t sm[];
    uint32_t* Qs = sm;
    uint32_t* Ks = sm + QWORDS;
    uint32_t* Vs = sm + QWORDS + KWORDS;
    uint32_t* Pw = sm + QWORDS + 2 * KWORDS;

    const int qt = blockIdx.x;
    const int h  = blockIdx.y;
    const int b  = blockIdx.z;
    const int tid  = threadIdx.x;
    const int warp = tid >> 5;
    const int lane = tid & 31;
    const int g = lane >> 2;
    const int t = lane & 3;
    const int q0 = qt * BQ;
    const int wrow0 = warp * 16;
    uint32_t* Ps = Pw + warp * 16 * PSTR;

    {
        const int qr = tid >> 1;
        const int dc = (tid & 1) * 32;
        const float* qg = g_q + (((size_t)(b * S_ + q0 + qr)) * H_ + h) * DH + dc;
        #pragma unroll
        for (int j = 0; j < 32; j += 4) {
            float4 v4 = *(const float4*)(qg + j);
            Qs[qr * PSTR + dc + j]     = f2tf32(v4.x);
            Qs[qr * PSTR + dc + j + 1] = f2tf32(v4.y);
            Qs[qr * PSTR + dc + j + 2] = f2tf32(v4.z);
            Qs[qr * PSTR + dc + j + 3] = f2tf32(v4.w);
        }
    }

    float o[8][4];
    #pragma unroll
    for (int nt = 0; nt < 8; nt++)
        #pragma unroll
        for (int r = 0; r < 4; r++) o[nt][r] = 0.f;
    float m0r = -INFINITY, m1r = -INFINITY, l0 = 0.f, l1 = 0.f;

    const int kc = tid & 63;
    const int dq = (tid >> 6) * 16;

    const int nkt = 2 * qt + 2;
    for (int kt = 0; kt < nkt; kt++) {
        const int k0 = kt * 64;

        float4 kr[4], vr[4];
        {
            const size_t goff = (((size_t)(b * S_ + k0 + kc)) * H_ + h) * DH + dq;
            const float* kg = g_k + goff;
            const float* vg = g_v + goff;
            #pragma unroll
            for (int j = 0; j < 4; j++) {
                kr[j] = *(const float4*)(kg + j * 4);
                vr[j] = *(const float4*)(vg + j * 4);
            }
        }
        __syncthreads();
        #pragma unroll
        for (int j = 0; j < 4; j++) {
            Ks[(dq + j * 4 + 0) * KSTR + kc] = f2tf32(kr[j].x);
            Ks[(dq + j * 4 + 1) * KSTR + kc] = f2tf32(kr[j].y);
            Ks[(dq + j * 4 + 2) * KSTR + kc] = f2tf32(kr[j].z);
            Ks[(dq + j * 4 + 3) * KSTR + kc] = f2tf32(kr[j].w);
        }
        #pragma unroll
        for (int j = 0; j < 4; j++) {
            uint4 u;
            u.x = f2tf32(vr[j].x); u.y = f2tf32(vr[j].y);
            u.z = f2tf32(vr[j].z); u.w = f2tf32(vr[j].w);
            *(uint4*)&Vs[kc * KSTR + dq + j * 4] = u;
        }
        __syncthreads();

        float s[8][4];
        #pragma unroll
        for (int nt = 0; nt < 8; nt++)
            #pragma unroll
            for (int r = 0; r < 4; r++) s[nt][r] = 0.f;

        #pragma unroll
        for (int ks = 0; ks < 8; ks++) {
            const int kb = ks * 8;
            uint32_t a0 = Qs[(wrow0 + g) * PSTR + kb + t];
            uint32_t a1 = Qs[(wrow0 + g + 8) * PSTR + kb + t];
            uint32_t a2 = Qs[(wrow0 + g) * PSTR + kb + t + 4];
            uint32_t a3 = Qs[(wrow0 + g + 8) * PSTR + kb + t + 4];
            #pragma unroll
            for (int nt = 0; nt < 8; nt++) {
                uint32_t b0 = Ks[(kb + t) * KSTR + nt * 8 + g];
                uint32_t b1 = Ks[(kb + t + 4) * KSTR + nt * 8 + g];
                MMA_TF32(s[nt][0], s[nt][1], s[nt][2], s[nt][3],
                         a0, a1, a2, a3, b0, b1);
            }
        }

        if (kt >= 2 * qt) {
            const int row0 = q0 + wrow0 + g;
            #pragma unroll
            for (int nt = 0; nt < 8; nt++) {
                const int col = k0 + nt * 8 + 2 * t;
                if (col     > row0)     s[nt][0] = -INFINITY;
                if (col + 1 > row0)     s[nt][1] = -INFINITY;
                if (col     > row0 + 8) s[nt][2] = -INFINITY;
                if (col + 1 > row0 + 8) s[nt][3] = -INFINITY;
            }
        }

        float mx0 = -INFINITY, mx1 = -INFINITY;
        #pragma unroll
        for (int nt = 0; nt < 8; nt++) {
            mx0 = fmaxf(mx0, fmaxf(s[nt][0], s[nt][1]));
            mx1 = fmaxf(mx1, fmaxf(s[nt][2], s[nt][3]));
        }
        mx0 = fmaxf(mx0, __shfl_xor_sync(0xffffffffu, mx0, 1));
        mx0 = fmaxf(mx0, __shfl_xor_sync(0xffffffffu, mx0, 2));
        mx1 = fmaxf(mx1, __shfl_xor_sync(0xffffffffu, mx1, 1));
        mx1 = fmaxf(mx1, __shfl_xor_sync(0xffffffffu, mx1, 2));

        const float mn0 = fmaxf(m0r, mx0);
        const float mn1 = fmaxf(m1r, mx1);
        const float sc0 = __expf(m0r - mn0);
        const float sc1 = __expf(m1r - mn1);

        float ls0 = 0.f, ls1 = 0.f;
        #pragma unroll
        for (int nt = 0; nt < 8; nt++) {
            float p0 = __expf(s[nt][0] - mn0);
            float p1 = __expf(s[nt][1] - mn0);
            float p2 = __expf(s[nt][2] - mn1);
            float p3 = __expf(s[nt][3] - mn1);
            ls0 += p0 + p1;
            ls1 += p2 + p3;
            uint2 u01 = make_uint2(f2tf32(p0), f2tf32(p1));
            uint2 u23 = make_uint2(f2tf32(p2), f2tf32(p3));
            *(uint2*)&Ps[g * PSTR + nt * 8 + 2 * t]       = u01;
            *(uint2*)&Ps[(g + 8) * PSTR + nt * 8 + 2 * t] = u23;
        }
        ls0 += __shfl_xor_sync(0xffffffffu, ls0, 1);
        ls0 += __shfl_xor_sync(0xffffffffu, ls0, 2);
        ls1 += __shfl_xor_sync(0xffffffffu, ls1, 1);
        ls1 += __shfl_xor_sync(0xffffffffu, ls1, 2);
        l0 = l0 * sc0 + ls0;
        l1 = l1 * sc1 + ls1;
        #pragma unroll
        for (int nt = 0; nt < 8; nt++) {
            o[nt][0] *= sc0; o[nt][1] *= sc0;
            o[nt][2] *= sc1; o[nt][3] *= sc1;
        }
        m0r = mn0; m1r = mn1;

        __syncwarp();

        #pragma unroll
        for (int ks = 0; ks < 8; ks++) {
            const int kb = ks * 8;
            uint32_t a0 = Ps[g * PSTR + kb + t];
            uint32_t a1 = Ps[(g + 8) * PSTR + kb + t];
            uint32_t a2 = Ps[g * PSTR + kb + t + 4];
            uint32_t a3 = Ps[(g + 8) * PSTR + kb + t + 4];
            #pragma unroll
            for (int nt = 0; nt < 8; nt++) {
                uint32_t b0 = Vs[(kb + t) * KSTR + nt * 8 + g];
                uint32_t b1 = Vs[(kb + t + 4) * KSTR + nt * 8 + g];
                MMA_TF32(o[nt][0], o[nt][1], o[nt][2], o[nt][3],
                         a0, a1, a2, a3, b0, b1);
            }
        }
        __syncwarp();
    }

    // writeback: fp16 (consumed as mma A operand by out-proj GEMM)
    const float i0 = 1.f / l0;
    const float i1 = 1.f / l1;
    __half* xg0 = g_xh + (((size_t)(b * S_ + q0 + wrow0 + g)) * H_ + h) * DH;
    __half* xg1 = xg0 + (size_t)8 * H_ * DH;
    #pragma unroll
    for (int nt = 0; nt < 8; nt++) {
        __half2 h0 = __floats2half2_rn(o[nt][0] * i0, o[nt][1] * i0);
        __half2 h1 = __floats2half2_rn(o[nt][2] * i1, o[nt][3] * i1);
        *(__half2*)(xg0 + nt * 8 + 2 * t) = h0;
        *(__half2*)(xg1 + nt * 8 + 2 * t) = h1;
    }
}

// ---------------------------------------------------------------------------
extern "C" void kernel_launch(void* const* d_in, const int* in_sizes, int n_in,
                              void* d_out, int out_size)
{
    (void)in_sizes; (void)n_in; (void)out_size;
    const float* inputs = (const float*)d_in[0];
    const float* w_q    = (const float*)d_in[1];
    const float* w_k    = (const float*)d_in[2];
    const float* w_v    = (const float*)d_in[3];
    const float* w_out  = (const float*)d_in[4];
    const int*   segpos = (const int*)d_in[5];
    float* out = (float*)d_out;

    float *q, *k, *v;
    __half *ah, *wth, *xh;
    cudaGetSymbolAddress((void**)&q, g_q);
    cudaGetSymbolAddress((void**)&k, g_k);
    cudaGetSymbolAddress((void**)&v, g_v);
    cudaGetSymbolAddress((void**)&ah, g_ah);
    cudaGetSymbolAddress((void**)&wth, g_wth);
    cudaGetSymbolAddress((void**)&xh, g_xh);

    to_half<<<B_ * S_ * D_ / (256 * 8), 256>>>(inputs, ah);
    transpose_half<<<dim3(32, 32, 4), dim3(32, 8)>>>(w_q, w_k, w_v, w_out, wth);

    cudaFuncSetAttribute(gemm_h, cudaFuncAttributeMaxDynamicSharedMemorySize, GSMEM_BYTES);
    // fused QKV: N = 3072
    gemm_h<<<dim3(24, 64), 256, GSMEM_BYTES>>>(ah, wth, q, k, v);

    const int rope_threads = B_ * S_ * H_ * (DH / 2);
    rope_kernel<<<rope_threads / 256, 256>>>(q, k, segpos);

    const int fsmem = FTC_SMEM_WORDS * (int)sizeof(uint32_t);
    cudaFuncSetAttribute(flash_tc, cudaFuncAttributeMaxDynamicSharedMemorySize, fsmem);
    flash_tc<<<dim3(S_ / BQ, H_, B_), 256, fsmem>>>();

    // out-projection: N = 1024
    gemm_h<<<dim3(8, 64), 256, GSMEM_BYTES>>>(xh, wth + (size_t)3 * 1024 * 1024, out, out, out);
}

// round 9
// speedup vs baseline: 13.6451x; 1.3624x over previous
#include <cuda_runtime.h>
#include <cuda_fp16.h>
#include <math.h>
#include <stdint.h>

#define B_ 4
#define S_ 2048
#define D_ 1024
#define H_ 16
#define DH 64

__device__ float  g_q[B_*S_*H_*DH];      // fp32 q (pre-rope)
__device__ float  g_k[B_*S_*H_*DH];      // fp32 k (pre-rope)
__device__ __half g_qh[B_*S_*H_*DH];     // fp16 q (post-rope, scaled)
__device__ __half g_kh[B_*S_*H_*DH];     // fp16 k (post-rope)
__device__ __half g_vh[B_*S_*H_*DH];     // fp16 v
__device__ __half g_xh[B_*S_*H_*DH];     // flash out (A of out-proj)
__device__ __half g_ah[B_*S_*D_];        // fp16 inputs
__device__ __half g_wth[4*1024*1024];    // transposed fp16 weights

__device__ __forceinline__ uint32_t smem_u32(const void* p) {
    uint32_t a;
    asm("{ .reg .u64 t; cvta.to.shared.u64 t, %1; cvt.u32.u64 %0, t; }" : "=r"(a) : "l"(p));
    return a;
}

#define MMA_F16(c0,c1,c2,c3,a0,a1,a2,a3,b0,b1)                           \
    asm volatile(                                                        \
        "mma.sync.aligned.m16n8k16.row.col.f32.f16.f16.f32 "             \
        "{%0,%1,%2,%3}, {%4,%5,%6,%7}, {%8,%9}, {%0,%1,%2,%3};"          \
        : "+f"(c0), "+f"(c1), "+f"(c2), "+f"(c3)                         \
        : "r"(a0), "r"(a1), "r"(a2), "r"(a3), "r"(b0), "r"(b1))

#define CP16(dst, src) asm volatile("cp.async.cg.shared.global [%0], [%1], 16;" :: "r"(dst), "l"(src))
#define CP_COMMIT()    asm volatile("cp.async.commit_group;" ::: "memory")
#define CP_WAIT2()     asm volatile("cp.async.wait_group 2;" ::: "memory")

// ---------------------------------------------------------------------------
__global__ __launch_bounds__(256) void to_half(
    const float* __restrict__ src, __half* __restrict__ dst)
{
    const size_t i = (size_t)(blockIdx.x * blockDim.x + threadIdx.x) * 8;
    float4 v0 = *(const float4*)(src + i);
    float4 v1 = *(const float4*)(src + i + 4);
    __half2 h[4];
    h[0] = __floats2half2_rn(v0.x, v0.y);
    h[1] = __floats2half2_rn(v0.z, v0.w);
    h[2] = __floats2half2_rn(v1.x, v1.y);
    h[3] = __floats2half2_rn(v1.z, v1.w);
    *(uint4*)(dst + i) = *(uint4*)h;
}

__global__ __launch_bounds__(256) void transpose_half(
    const float* __restrict__ w0, const float* __restrict__ w1,
    const float* __restrict__ w2, const float* __restrict__ w3,
    __half* __restrict__ dst)
{
    __shared__ float tile[32][33];
    const int z = blockIdx.z;
    const float* src = (z == 0) ? w0 : (z == 1) ? w1 : (z == 2) ? w2 : w3;
    __half* out = dst + (size_t)z * 1024 * 1024;
    const int n0 = blockIdx.x * 32;
    const int k0 = blockIdx.y * 32;
    const int tx = threadIdx.x;
    const int ty = threadIdx.y;

    #pragma unroll
    for (int j = 0; j < 4; j++)
        tile[ty + j * 8][tx] = src[(size_t)(k0 + ty + j * 8) * 1024 + n0 + tx];
    __syncthreads();
    #pragma unroll
    for (int j = 0; j < 4; j++)
        out[(size_t)(n0 + ty + j * 8) * 1024 + k0 + tx] = __float2half(tile[tx][ty + j * 8]);
}

// ---------------------------------------------------------------------------
// fp16 mma GEMM, BK=32 halves, 4-stage cp.async, 32 iterations.
// C[8192,N] = A[8192,1024] @ Bt[N,1024]^T. sel: 0->Cq f32, 1->Ck f32, 2->Cvh f16.
// Row = 32 halves (64 B) in 20-word (80 B) stride; conflict-free fragment LDS.
// Each thread stages 32 B of one row: src +(tid&1)*16 halves, chunks +0/+8 halves;
// dst +(tid&1)*32 bytes, chunks +0/+16 bytes.
// ---------------------------------------------------------------------------
#define GSTR 20
#define STG_WORDS (128 * GSTR)                 // 2560 words = 10240 B / stage
#define GSMEM_BYTES (8 * STG_WORDS * 4)        // 80 KB

__global__ __launch_bounds__(256) void gemm_h(
    const __half* __restrict__ A, const __half* __restrict__ Bt,
    float* __restrict__ Cq, float* __restrict__ Ck, __half* __restrict__ Cvh)
{
    extern __shared__ uint32_t smw[];
    const uint32_t sbase = smem_u32(smw);

    const int tid  = threadIdx.x;
    const int warp = tid >> 5;
    const int lane = tid & 31;
    const int g = lane >> 2;
    const int t = lane & 3;
    const int wm = warp >> 1;
    const int wn = warp & 1;

    const int m0 = blockIdx.y * 128;
    const int n0 = blockIdx.x * 128;
    const int sel  = n0 >> 10;
    const int col0 = n0 & 1023;

    const int lrow = tid >> 1;
    const int hh   = (tid & 1) * 16;   // half offset within the 32-half row
    const __half* ag = A  + (size_t)(m0 + lrow) * 1024 + hh;
    const __half* bg = Bt + (size_t)(n0 + lrow) * 1024 + hh;
    const uint32_t adst = sbase + (uint32_t)(lrow * 80 + hh * 2);
    const uint32_t bdst = adst + 4 * STG_WORDS * 4;

    float c[2][8][4];
    #pragma unroll
    for (int mt = 0; mt < 2; mt++)
        #pragma unroll
        for (int nt = 0; nt < 8; nt++)
            #pragma unroll
            for (int r = 0; r < 4; r++) c[mt][nt][r] = 0.f;

    #pragma unroll
    for (int s = 0; s < 3; s++) {
        CP16(adst + s * 10240,      ag + s * 32);
        CP16(adst + s * 10240 + 16, ag + s * 32 + 8);
        CP16(bdst + s * 10240,      bg + s * 32);
        CP16(bdst + s * 10240 + 16, bg + s * 32 + 8);
        CP_COMMIT();
    }

    for (int kt = 0; kt < 32; kt++) {
        CP_WAIT2();
        __syncthreads();

        if (kt + 3 < 32) {
            const int s = (kt + 3) & 3;
            CP16(adst + s * 10240,      ag + (kt + 3) * 32);
            CP16(adst + s * 10240 + 16, ag + (kt + 3) * 32 + 8);
            CP16(bdst + s * 10240,      bg + (kt + 3) * 32);
            CP16(bdst + s * 10240 + 16, bg + (kt + 3) * 32 + 8);
        }
        CP_COMMIT();

        const int buf = kt & 3;
        const uint32_t* As = smw + buf * STG_WORDS;
        const uint32_t* Bs = smw + 4 * STG_WORDS + buf * STG_WORDS;

        #pragma unroll
        for (int ks = 0; ks < 2; ks++) {
            const int kb = ks * 8;
            uint32_t afr[2][4];
            #pragma unroll
            for (int mt = 0; mt < 2; mt++) {
                const int rb = wm * 32 + mt * 16 + g;
                afr[mt][0] = As[rb * GSTR + kb + t];
                afr[mt][1] = As[(rb + 8) * GSTR + kb + t];
                afr[mt][2] = As[rb * GSTR + kb + t + 4];
                afr[mt][3] = As[(rb + 8) * GSTR + kb + t + 4];
            }
            uint32_t bfr[8][2];
            #pragma unroll
            for (int nt = 0; nt < 8; nt++) {
                const int cb = wn * 64 + nt * 8 + g;
                bfr[nt][0] = Bs[cb * GSTR + kb + t];
                bfr[nt][1] = Bs[cb * GSTR + kb + t + 4];
            }
            #pragma unroll
            for (int mt = 0; mt < 2; mt++)
                #pragma unroll
                for (int nt = 0; nt < 8; nt++)
                    MMA_F16(c[mt][nt][0], c[mt][nt][1], c[mt][nt][2], c[mt][nt][3],
                            afr[mt][0], afr[mt][1], afr[mt][2], afr[mt][3],
                            bfr[nt][0], bfr[nt][1]);
        }
    }

    if (sel == 2) {
        #pragma unroll
        for (int mt = 0; mt < 2; mt++) {
            const int r = m0 + wm * 32 + mt * 16 + g;
            #pragma unroll
            for (int nt = 0; nt < 8; nt++) {
                const int cc = col0 + wn * 64 + nt * 8 + t * 2;
                *(__half2*)(Cvh + (size_t)r * 1024 + cc) =
                    __floats2half2_rn(c[mt][nt][0], c[mt][nt][1]);
                *(__half2*)(Cvh + (size_t)(r + 8) * 1024 + cc) =
                    __floats2half2_rn(c[mt][nt][2], c[mt][nt][3]);
            }
        }
    } else {
        float* C = (sel == 0) ? Cq : Ck;
        #pragma unroll
        for (int mt = 0; mt < 2; mt++) {
            const int r = m0 + wm * 32 + mt * 16 + g;
            #pragma unroll
            for (int nt = 0; nt < 8; nt++) {
                const int cc = col0 + wn * 64 + nt * 8 + t * 2;
                *(float2*)(C + (size_t)r * 1024 + cc)       = make_float2(c[mt][nt][0], c[mt][nt][1]);
                *(float2*)(C + (size_t)(r + 8) * 1024 + cc) = make_float2(c[mt][nt][2], c[mt][nt][3]);
            }
        }
    }
}

// ---------------------------------------------------------------------------
// RoPE: fp32 q,k -> fp16 q(scaled),k.
// ---------------------------------------------------------------------------
__global__ __launch_bounds__(256) void rope_kernel(
    const float* __restrict__ q, const float* __restrict__ k,
    __half* __restrict__ qh, __half* __restrict__ kh,
    const int* __restrict__ segpos)
{
    const int idx = blockIdx.x * blockDim.x + threadIdx.x;
    const int d = idx & 31;
    const int rest = idx >> 5;
    const int bs = rest >> 4;

    const int p = segpos[bs];
    const float ang = (float)p * expf(-(float)d * 0.28782313662425574f);
    float sv, cv;
    sincosf(ang, &sv, &cv);

    const size_t base = (size_t)rest * 64 + d;
    float q1 = q[base], q2 = q[base + 32];
    qh[base]      = __float2half((q1 * cv - q2 * sv) * 0.125f);
    qh[base + 32] = __float2half((q2 * cv + q1 * sv) * 0.125f);
    float k1 = k[base], k2 = k[base + 32];
    kh[base]      = __float2half(k1 * cv - k2 * sv);
    kh[base + 32] = __float2half(k2 * cv + k1 * sv);
}

// ---------------------------------------------------------------------------
// fp16-mma flash attention. CTA: 128 q-rows x (b,h); 8 warps, warp tile 16x64.
// Qs: [128][QSTR] half2 words (dh pairs). Ks: [dhpair][kc] stride 72.
// Vs: [kvpair][dh] stride 72 (word = V[2p][d],V[2p+1][d]). Ps per-warp.
// ---------------------------------------------------------------------------
#define BQ 128
#define QSTR 36
#define KSTR2 72
#define VSTR2 72
#define PSTR2 36
#define QW2 (BQ * QSTR)            // 4608
#define KW2 (32 * KSTR2)           // 2304
#define VW2 (32 * VSTR2)           // 2304
#define PW2 (8 * 16 * PSTR2)       // 4608
#define FH_SMEM_WORDS (QW2 + KW2 + VW2 + PW2)

__global__ __launch_bounds__(256) void flash_h()
{
    extern __shared__ uint32_t sm[];
    uint32_t* Qs = sm;
    uint32_t* Ks = sm + QW2;
    uint32_t* Vs = sm + QW2 + KW2;
    uint32_t* Pw = sm + QW2 + KW2 + VW2;

    const int qt = blockIdx.x;
    const int h  = blockIdx.y;
    const int b  = blockIdx.z;
    const int tid  = threadIdx.x;
    const int warp = tid >> 5;
    const int lane = tid & 31;
    const int g = lane >> 2;
    const int t = lane & 3;
    const int q0 = qt * BQ;
    const int wrow0 = warp * 16;
    uint32_t* Ps = Pw + warp * 16 * PSTR2;

    // stage Q: row tid/2, 32-half block (tid&1)
    {
        const int qr = tid >> 1;
        const int hc = (tid & 1) * 16;   // half2-word offset
        const __half* qg = g_qh + (((size_t)(b * S_ + q0 + qr)) * H_ + h) * DH + hc * 2;
        uint4 u0 = *(const uint4*)(qg);
        uint4 u1 = *(const uint4*)(qg + 8);
        uint4 u2 = *(const uint4*)(qg + 16);
        uint4 u3 = *(const uint4*)(qg + 24);
        *(uint4*)&Qs[qr * QSTR + hc]      = u0;
        *(uint4*)&Qs[qr * QSTR + hc + 4]  = u1;
        *(uint4*)&Qs[qr * QSTR + hc + 8]  = u2;
        *(uint4*)&Qs[qr * QSTR + hc + 12] = u3;
    }

    float o[8][4];
    #pragma unroll
    for (int nt = 0; nt < 8; nt++)
        #pragma unroll
        for (int r = 0; r < 4; r++) o[nt][r] = 0.f;
    float m0r = -INFINITY, m1r = -INFINITY, l0 = 0.f, l1 = 0.f;

    const int kc = tid & 63;           // K staging: kv column
    const int dq = (tid >> 6) * 16;    // K staging: dh quarter
    const int vp = tid & 31;           // V staging: kv pair
    const int vd = (tid >> 5) * 8;     // V staging: 8 dh columns

    const int nkt = 2 * qt + 2;
    for (int kt = 0; kt < nkt; kt++) {
        const int k0 = kt * 64;

        uint4 kr0, kr1, va, vb;
        {
            const __half* kg = g_kh + (((size_t)(b * S_ + k0 + kc)) * H_ + h) * DH + dq;
            kr0 = *(const uint4*)(kg);
            kr1 = *(const uint4*)(kg + 8);
            const __half* vg0 = g_vh + (((size_t)(b * S_ + k0 + 2 * vp)) * H_ + h) * DH + vd;
            const __half* vg1 = vg0 + (size_t)H_ * DH;
            va = *(const uint4*)(vg0);
            vb = *(const uint4*)(vg1);
        }
        __syncthreads();
        {
            const uint32_t* kw = (const uint32_t*)&kr0;
            #pragma unroll
            for (int j = 0; j < 4; j++)
                Ks[(dq / 2 + j) * KSTR2 + kc] = kw[j];
            const uint32_t* kw1 = (const uint32_t*)&kr1;
            #pragma unroll
            for (int j = 0; j < 4; j++)
                Ks[(dq / 2 + 4 + j) * KSTR2 + kc] = kw1[j];
        }
        {
            const __half* ha = (const __half*)&va;
            const __half* hb = (const __half*)&vb;
            uint32_t w[8];
            #pragma unroll
            for (int j = 0; j < 8; j++) {
                __half2 hh = __halves2half2(ha[j], hb[j]);
                w[j] = *(uint32_t*)&hh;
            }
            *(uint4*)&Vs[vp * VSTR2 + vd]     = *(uint4*)&w[0];
            *(uint4*)&Vs[vp * VSTR2 + vd + 4] = *(uint4*)&w[4];
        }
        __syncthreads();

        // S = Q @ K^T : 4 ksteps of k16
        float s[8][4];
        #pragma unroll
        for (int nt = 0; nt < 8; nt++)
            #pragma unroll
            for (int r = 0; r < 4; r++) s[nt][r] = 0.f;

        #pragma unroll
        for (int ks = 0; ks < 4; ks++) {
            const int kb = ks * 8;
            uint32_t a0 = Qs[(wrow0 + g) * QSTR + kb + t];
            uint32_t a1 = Qs[(wrow0 + g + 8) * QSTR + kb + t];
            uint32_t a2 = Qs[(wrow0 + g) * QSTR + kb + t + 4];
            uint32_t a3 = Qs[(wrow0 + g + 8) * QSTR + kb + t + 4];
            #pragma unroll
            for (int nt = 0; nt < 8; nt++) {
                uint32_t b0 = Ks[(kb + t) * KSTR2 + nt * 8 + g];
                uint32_t b1 = Ks[(kb + t + 4) * KSTR2 + nt * 8 + g];
                MMA_F16(s[nt][0], s[nt][1], s[nt][2], s[nt][3],
                        a0, a1, a2, a3, b0, b1);
            }
        }

        if (kt >= 2 * qt) {
            const int row0 = q0 + wrow0 + g;
            #pragma unroll
            for (int nt = 0; nt < 8; nt++) {
                const int col = k0 + nt * 8 + 2 * t;
                if (col     > row0)     s[nt][0] = -INFINITY;
                if (col + 1 > row0)     s[nt][1] = -INFINITY;
                if (col     > row0 + 8) s[nt][2] = -INFINITY;
                if (col + 1 > row0 + 8) s[nt][3] = -INFINITY;
            }
        }

        float mx0 = -INFINITY, mx1 = -INFINITY;
        #pragma unroll
        for (int nt = 0; nt < 8; nt++) {
            mx0 = fmaxf(mx0, fmaxf(s[nt][0], s[nt][1]));
            mx1 = fmaxf(mx1, fmaxf(s[nt][2], s[nt][3]));
        }
        mx0 = fmaxf(mx0, __shfl_xor_sync(0xffffffffu, mx0, 1));
        mx0 = fmaxf(mx0, __shfl_xor_sync(0xffffffffu, mx0, 2));
        mx1 = fmaxf(mx1, __shfl_xor_sync(0xffffffffu, mx1, 1));
        mx1 = fmaxf(mx1, __shfl_xor_sync(0xffffffffu, mx1, 2));

        const float mn0 = fmaxf(m0r, mx0);
        const float mn1 = fmaxf(m1r, mx1);
        const float sc0 = __expf(m0r - mn0);
        const float sc1 = __expf(m1r - mn1);

        float ls0 = 0.f, ls1 = 0.f;
        #pragma unroll
        for (int nt = 0; nt < 8; nt++) {
            float p0 = __expf(s[nt][0] - mn0);
            float p1 = __expf(s[nt][1] - mn0);
            float p2 = __expf(s[nt][2] - mn1);
            float p3 = __expf(s[nt][3] - mn1);
            ls0 += p0 + p1;
            ls1 += p2 + p3;
            __half2 h01 = __floats2half2_rn(p0, p1);
            __half2 h23 = __floats2half2_rn(p2, p3);
            Ps[g * PSTR2 + nt * 4 + t]       = *(uint32_t*)&h01;
            Ps[(g + 8) * PSTR2 + nt * 4 + t] = *(uint32_t*)&h23;
        }
        ls0 += __shfl_xor_sync(0xffffffffu, ls0, 1);
        ls0 += __shfl_xor_sync(0xffffffffu, ls0, 2);
        ls1 += __shfl_xor_sync(0xffffffffu, ls1, 1);
        ls1 += __shfl_xor_sync(0xffffffffu, ls1, 2);
        l0 = l0 * sc0 + ls0;
        l1 = l1 * sc1 + ls1;
        #pragma unroll
        for (int nt = 0; nt < 8; nt++) {
            o[nt][0] *= sc0; o[nt][1] *= sc0;
            o[nt][2] *= sc1; o[nt][3] *= sc1;
        }
        m0r = mn0; m1r = mn1;

        __syncwarp();

        // O += P @ V : 4 ksteps of kv16
        #pragma unroll
        for (int ks = 0; ks < 4; ks++) {
            const int kb = ks * 8;
            uint32_t a0 = Ps[g * PSTR2 + kb + t];
            uint32_t a1 = Ps[(g + 8) * PSTR2 + kb + t];
            uint32_t a2 = Ps[g * PSTR2 + kb + t + 4];
            uint32_t a3 = Ps[(g + 8) * PSTR2 + kb + t + 4];
            #pragma unroll
            for (int nt = 0; nt < 8; nt++) {
                uint32_t b0 = Vs[(kb + t) * VSTR2 + nt * 8 + g];
                uint32_t b1 = Vs[(kb + t + 4) * VSTR2 + nt * 8 + g];
                MMA_F16(o[nt][0], o[nt][1], o[nt][2], o[nt][3],
                        a0, a1, a2, a3, b0, b1);
            }
        }
        __syncwarp();
    }

    const float i0 = 1.f / l0;
    const float i1 = 1.f / l1;
    __half* xg0 = g_xh + (((size_t)(b * S_ + q0 + wrow0 + g)) * H_ + h) * DH;
    __half* xg1 = xg0 + (size_t)8 * H_ * DH;
    #pragma unroll
    for (int nt = 0; nt < 8; nt++) {
        *(__half2*)(xg0 + nt * 8 + 2 * t) = __floats2half2_rn(o[nt][0] * i0, o[nt][1] * i0);
        *(__half2*)(xg1 + nt * 8 + 2 * t) = __floats2half2_rn(o[nt][2] * i1, o[nt][3] * i1);
    }
}

// ---------------------------------------------------------------------------
extern "C" void kernel_launch(void* const* d_in, const int* in_sizes, int n_in,
                              void* d_out, int out_size)
{
    (void)in_sizes; (void)n_in; (void)out_size;
    const float* inputs = (const float*)d_in[0];
    const float* w_q    = (const float*)d_in[1];
    const float* w_k    = (const float*)d_in[2];
    const float* w_v    = (const float*)d_in[3];
    const float* w_out  = (const float*)d_in[4];
    const int*   segpos = (const int*)d_in[5];
    float* out = (float*)d_out;

    float *q, *k;
    __half *qh, *kh, *vh, *xh, *ah, *wth;
    cudaGetSymbolAddress((void**)&q, g_q);
    cudaGetSymbolAddress((void**)&k, g_k);
    cudaGetSymbolAddress((void**)&qh, g_qh);
    cudaGetSymbolAddress((void**)&kh, g_kh);
    cudaGetSymbolAddress((void**)&vh, g_vh);
    cudaGetSymbolAddress((void**)&xh, g_xh);
    cudaGetSymbolAddress((void**)&ah, g_ah);
    cudaGetSymbolAddress((void**)&wth, g_wth);

    to_half<<<B_ * S_ * D_ / (256 * 8), 256>>>(inputs, ah);
    transpose_half<<<dim3(32, 32, 4), dim3(32, 8)>>>(w_q, w_k, w_v, w_out, wth);

    cudaFuncSetAttribute(gemm_h, cudaFuncAttributeMaxDynamicSharedMemorySize, GSMEM_BYTES);
    // fused QKV: N = 3072 (sel 0->q fp32, 1->k fp32, 2->v fp16)
    gemm_h<<<dim3(24, 64), 256, GSMEM_BYTES>>>(ah, wth, q, k, vh);

    const int rope_threads = B_ * S_ * H_ * (DH / 2);
    rope_kernel<<<rope_threads / 256, 256>>>(q, k, qh, kh, segpos);

    const int fsmem = FH_SMEM_WORDS * (int)sizeof(uint32_t);
    cudaFuncSetAttribute(flash_h, cudaFuncAttributeMaxDynamicSharedMemorySize, fsmem);
    flash_h<<<dim3(S_ / BQ, H_, B_), 256, fsmem>>>();

    // out-projection: N = 1024, n0 < 1024 -> sel = 0 -> routes to out
    gemm_h<<<dim3(8, 64), 256, GSMEM_BYTES>>>(xh, wth + (size_t)3 * 1024 * 1024,
                                              out, nullptr, nullptr);
}

// round 10
// speedup vs baseline: 15.7774x; 1.1563x over previous
#include <cuda_runtime.h>
#include <cuda_fp16.h>
#include <math.h>
#include <stdint.h>

#define B_ 4
#define S_ 2048
#define D_ 1024
#define H_ 16
#define DH 64

__device__ __half g_qh[B_*S_*H_*DH];     // fp16 q (post-rope, scaled)
__device__ __half g_kh[B_*S_*H_*DH];     // fp16 k (post-rope)
__device__ __half g_vh[B_*S_*H_*DH];     // fp16 v
__device__ __half g_xh[B_*S_*H_*DH];     // flash out (A of out-proj)
__device__ __half g_ah[B_*S_*D_];        // fp16 inputs
__device__ __half g_wth[4*1024*1024];    // transposed fp16 weights
__device__ float2 g_tab[S_*32];          // rope (sin,cos) table

__device__ __forceinline__ uint32_t smem_u32(const void* p) {
    uint32_t a;
    asm("{ .reg .u64 t; cvta.to.shared.u64 t, %1; cvt.u32.u64 %0, t; }" : "=r"(a) : "l"(p));
    return a;
}

#define MMA_F16(c0,c1,c2,c3,a0,a1,a2,a3,b0,b1)                           \
    asm volatile(                                                        \
        "mma.sync.aligned.m16n8k16.row.col.f32.f16.f16.f32 "             \
        "{%0,%1,%2,%3}, {%4,%5,%6,%7}, {%8,%9}, {%0,%1,%2,%3};"          \
        : "+f"(c0), "+f"(c1), "+f"(c2), "+f"(c3)                         \
        : "r"(a0), "r"(a1), "r"(a2), "r"(a3), "r"(b0), "r"(b1))

#define LDSM4(r0,r1,r2,r3,a)                                             \
    asm volatile("ldmatrix.sync.aligned.m8n8.x4.shared.b16 "             \
        "{%0,%1,%2,%3}, [%4];"                                           \
        : "=r"(r0), "=r"(r1), "=r"(r2), "=r"(r3) : "r"(a))

#define CP16(dst, src) asm volatile("cp.async.cg.shared.global [%0], [%1], 16;" :: "r"(dst), "l"(src))
#define CP_COMMIT()    asm volatile("cp.async.commit_group;" ::: "memory")
#define CP_WAIT2()     asm volatile("cp.async.wait_group 2;" ::: "memory")

// ---------------------------------------------------------------------------
__global__ __launch_bounds__(256) void build_tab()
{
    const int idx = blockIdx.x * 256 + threadIdx.x;   // 65536
    const int s = idx >> 5;
    const int d = idx & 31;
    const float ang = (float)s * expf(-(float)d * 0.28782313662425574f);
    float sv, cv;
    sincosf(ang, &sv, &cv);
    g_tab[idx] = make_float2(sv, cv);
}

__global__ __launch_bounds__(256) void to_half(
    const float* __restrict__ src, __half* __restrict__ dst)
{
    const size_t i = (size_t)(blockIdx.x * blockDim.x + threadIdx.x) * 8;
    float4 v0 = *(const float4*)(src + i);
    float4 v1 = *(const float4*)(src + i + 4);
    __half2 h[4];
    h[0] = __floats2half2_rn(v0.x, v0.y);
    h[1] = __floats2half2_rn(v0.z, v0.w);
    h[2] = __floats2half2_rn(v1.x, v1.y);
    h[3] = __floats2half2_rn(v1.z, v1.w);
    *(uint4*)(dst + i) = *(uint4*)h;
}

__global__ __launch_bounds__(256) void transpose_half(
    const float* __restrict__ w0, const float* __restrict__ w1,
    const float* __restrict__ w2, const float* __restrict__ w3,
    __half* __restrict__ dst)
{
    __shared__ float tile[32][33];
    const int z = blockIdx.z;
    const float* src = (z == 0) ? w0 : (z == 1) ? w1 : (z == 2) ? w2 : w3;
    __half* out = dst + (size_t)z * 1024 * 1024;
    const int n0 = blockIdx.x * 32;
    const int k0 = blockIdx.y * 32;
    const int tx = threadIdx.x;
    const int ty = threadIdx.y;

    #pragma unroll
    for (int j = 0; j < 4; j++)
        tile[ty + j * 8][tx] = src[(size_t)(k0 + ty + j * 8) * 1024 + n0 + tx];
    __syncthreads();
    #pragma unroll
    for (int j = 0; j < 4; j++)
        out[(size_t)(n0 + ty + j * 8) * 1024 + k0 + tx] = __float2half(tile[tx][ty + j * 8]);
}

// ---------------------------------------------------------------------------
// fp16 mma GEMM, BK=32, 4-stage cp.async, ldmatrix fragment loads.
// fused=1 (QKV): sel 0 -> rope->qh (scaled), sel 1 -> rope->kh, sel 2 -> vh.
// fused=0: plain fp32 store to Cf.
// ---------------------------------------------------------------------------
#define GSTR 20
#define STG_WORDS (128 * GSTR)                 // 2560 words = 10240 B / stage
#define GSMEM_BYTES (8 * STG_WORDS * 4)        // 80 KB

__global__ __launch_bounds__(256) void gemm_h(
    const __half* __restrict__ A, const __half* __restrict__ Bt,
    float* __restrict__ Cf, __half* __restrict__ qh, __half* __restrict__ kh,
    __half* __restrict__ vh, const int* __restrict__ segpos, int fused)
{
    extern __shared__ uint32_t smw[];
    const uint32_t sbase = smem_u32(smw);

    const int tid  = threadIdx.x;
    const int warp = tid >> 5;
    const int lane = tid & 31;
    const int g = lane >> 2;
    const int t = lane & 3;
    const int wm = warp >> 1;
    const int wn = warp & 1;

    const int m0 = blockIdx.y * 128;
    const int n0 = blockIdx.x * 128;
    const int sel  = n0 >> 10;
    const int col0 = n0 & 1023;

    const int lrow = tid >> 1;
    const int hh   = (tid & 1) * 16;
    const __half* ag = A  + (size_t)(m0 + lrow) * 1024 + hh;
    const __half* bg = Bt + (size_t)(n0 + lrow) * 1024 + hh;
    const uint32_t adst = sbase + (uint32_t)(lrow * 80 + hh * 2);
    const uint32_t bdst = adst + 4 * STG_WORDS * 4;

    // ldmatrix per-lane byte offsets within a stage
    uint32_t aoff[2], boff[4];
    #pragma unroll
    for (int mt = 0; mt < 2; mt++)
        aoff[mt] = (uint32_t)(((wm * 32 + mt * 16 + (lane & 15)) * 20
                               + ((lane & 16) ? 4 : 0)) * 4);
    #pragma unroll
    for (int j = 0; j < 4; j++)
        boff[j] = (uint32_t)(((wn * 64 + j * 16 + (lane & 7) + ((lane & 16) ? 8 : 0)) * 20
                              + ((lane & 8) ? 4 : 0)) * 4);

    float c[2][8][4];
    #pragma unroll
    for (int mt = 0; mt < 2; mt++)
        #pragma unroll
        for (int nt = 0; nt < 8; nt++)
            #pragma unroll
            for (int r = 0; r < 4; r++) c[mt][nt][r] = 0.f;

    #pragma unroll
    for (int s = 0; s < 3; s++) {
        CP16(adst + s * 10240,      ag + s * 32);
        CP16(adst + s * 10240 + 16, ag + s * 32 + 8);
        CP16(bdst + s * 10240,      bg + s * 32);
        CP16(bdst + s * 10240 + 16, bg + s * 32 + 8);
        CP_COMMIT();
    }

    for (int kt = 0; kt < 32; kt++) {
        CP_WAIT2();
        __syncthreads();

        if (kt + 3 < 32) {
            const int s = (kt + 3) & 3;
            CP16(adst + s * 10240,      ag + (kt + 3) * 32);
            CP16(adst + s * 10240 + 16, ag + (kt + 3) * 32 + 8);
            CP16(bdst + s * 10240,      bg + (kt + 3) * 32);
            CP16(bdst + s * 10240 + 16, bg + (kt + 3) * 32 + 8);
        }
        CP_COMMIT();

        const int buf = kt & 3;
        const uint32_t abuf = sbase + (uint32_t)(buf * 10240);
        const uint32_t bbuf = abuf + 4 * STG_WORDS * 4;

        #pragma unroll
        for (int ks = 0; ks < 2; ks++) {
            const uint32_t kbyte = ks * 32;
            uint32_t afr[2][4];
            #pragma unroll
            for (int mt = 0; mt < 2; mt++)
                LDSM4(afr[mt][0], afr[mt][1], afr[mt][2], afr[mt][3],
                      abuf + aoff[mt] + kbyte);
            uint32_t bfr[8][2];
            #pragma unroll
            for (int j = 0; j < 4; j++)
                LDSM4(bfr[2*j][0], bfr[2*j][1], bfr[2*j+1][0], bfr[2*j+1][1],
                      bbuf + boff[j] + kbyte);
            #pragma unroll
            for (int mt = 0; mt < 2; mt++)
                #pragma unroll
                for (int nt = 0; nt < 8; nt++)
                    MMA_F16(c[mt][nt][0], c[mt][nt][1], c[mt][nt][2], c[mt][nt][3],
                            afr[mt][0], afr[mt][1], afr[mt][2], afr[mt][3],
                            bfr[nt][0], bfr[nt][1]);
        }
    }

    if (!fused) {
        #pragma unroll
        for (int mt = 0; mt < 2; mt++) {
            const int r = m0 + wm * 32 + mt * 16 + g;
            #pragma unroll
            for (int nt = 0; nt < 8; nt++) {
                const int cc = col0 + wn * 64 + nt * 8 + t * 2;
                *(float2*)(Cf + (size_t)r * 1024 + cc)       = make_float2(c[mt][nt][0], c[mt][nt][1]);
                *(float2*)(Cf + (size_t)(r + 8) * 1024 + cc) = make_float2(c[mt][nt][2], c[mt][nt][3]);
            }
        }
    } else if (sel == 2) {
        #pragma unroll
        for (int mt = 0; mt < 2; mt++) {
            const int r = m0 + wm * 32 + mt * 16 + g;
            #pragma unroll
            for (int nt = 0; nt < 8; nt++) {
                const int cc = col0 + wn * 64 + nt * 8 + t * 2;
                *(__half2*)(vh + (size_t)r * 1024 + cc) =
                    __floats2half2_rn(c[mt][nt][0], c[mt][nt][1]);
                *(__half2*)(vh + (size_t)(r + 8) * 1024 + cc) =
                    __floats2half2_rn(c[mt][nt][2], c[mt][nt][3]);
            }
        }
    } else {
        // fused rope: warp tile (64) == head width; pair (d, d+32) = (nt, nt+4)
        __half* dst = (sel == 0) ? qh : kh;
        const float scl = (sel == 0) ? 0.125f : 1.0f;
        #pragma unroll
        for (int mt = 0; mt < 2; mt++) {
            const int r = m0 + wm * 32 + mt * 16 + g;
            const int p0 = segpos[r];
            const int p1 = segpos[r + 8];
            #pragma unroll
            for (int nt = 0; nt < 4; nt++) {
                const int d = nt * 8 + t * 2;
                float4 t0 = *(const float4*)(&g_tab[p0 * 32 + d]);  // sin_d,cos_d,sin_d1,cos_d1
                float4 t1 = *(const float4*)(&g_tab[p1 * 32 + d]);
                const int cc = col0 + wn * 64 + nt * 8 + t * 2;
                // row r
                float f0 = (c[mt][nt][0] * t0.y - c[mt][nt+4][0] * t0.x) * scl;
                float s0 = (c[mt][nt+4][0] * t0.y + c[mt][nt][0] * t0.x) * scl;
                float f1 = (c[mt][nt][1] * t0.w - c[mt][nt+4][1] * t0.z) * scl;
                float s1 = (c[mt][nt+4][1] * t0.w + c[mt][nt][1] * t0.z) * scl;
                *(__half2*)(dst + (size_t)r * 1024 + cc)      = __floats2half2_rn(f0, f1);
                *(__half2*)(dst + (size_t)r * 1024 + cc + 32) = __floats2half2_rn(s0, s1);
                // row r+8
                f0 = (c[mt][nt][2] * t1.y - c[mt][nt+4][2] * t1.x) * scl;
                s0 = (c[mt][nt+4][2] * t1.y + c[mt][nt][2] * t1.x) * scl;
                f1 = (c[mt][nt][3] * t1.w - c[mt][nt+4][3] * t1.z) * scl;
                s1 = (c[mt][nt+4][3] * t1.w + c[mt][nt][3] * t1.z) * scl;
                *(__half2*)(dst + (size_t)(r + 8) * 1024 + cc)      = __floats2half2_rn(f0, f1);
                *(__half2*)(dst + (size_t)(r + 8) * 1024 + cc + 32) = __floats2half2_rn(s0, s1);
            }
        }
    }
}

// ---------------------------------------------------------------------------
// fp16-mma flash attention (R9), qt scheduled descending.
// ---------------------------------------------------------------------------
#define BQ 128
#define QSTR 36
#define KSTR2 72
#define VSTR2 72
#define PSTR2 36
#define QW2 (BQ * QSTR)
#define KW2 (32 * KSTR2)
#define VW2 (32 * VSTR2)
#define PW2 (8 * 16 * PSTR2)
#define FH_SMEM_WORDS (QW2 + KW2 + VW2 + PW2)

__global__ __launch_bounds__(256) void flash_h()
{
    extern __shared__ uint32_t sm[];
    uint32_t* Qs = sm;
    uint32_t* Ks = sm + QW2;
    uint32_t* Vs = sm + QW2 + KW2;
    uint32_t* Pw = sm + QW2 + KW2 + VW2;

    const int qt = (int)gridDim.x - 1 - (int)blockIdx.x;   // longest first
    const int h  = blockIdx.y;
    const int b  = blockIdx.z;
    const int tid  = threadIdx.x;
    const int warp = tid >> 5;
    const int lane = tid & 31;
    const int g = lane >> 2;
    const int t = lane & 3;
    const int q0 = qt * BQ;
    const int wrow0 = warp * 16;
    uint32_t* Ps = Pw + warp * 16 * PSTR2;

    {
        const int qr = tid >> 1;
        const int hc = (tid & 1) * 16;
        const __half* qg = g_qh + (((size_t)(b * S_ + q0 + qr)) * H_ + h) * DH + hc * 2;
        uint4 u0 = *(const uint4*)(qg);
        uint4 u1 = *(const uint4*)(qg + 8);
        uint4 u2 = *(const uint4*)(qg + 16);
        uint4 u3 = *(const uint4*)(qg + 24);
        *(uint4*)&Qs[qr * QSTR + hc]      = u0;
        *(uint4*)&Qs[qr * QSTR + hc + 4]  = u1;
        *(uint4*)&Qs[qr * QSTR + hc + 8]  = u2;
        *(uint4*)&Qs[qr * QSTR + hc + 12] = u3;
    }

    float o[8][4];
    #pragma unroll
    for (int nt = 0; nt < 8; nt++)
        #pragma unroll
        for (int r = 0; r < 4; r++) o[nt][r] = 0.f;
    float m0r = -INFINITY, m1r = -INFINITY, l0 = 0.f, l1 = 0.f;

    const int kc = tid & 63;
    const int dq = (tid >> 6) * 16;
    const int vp = tid & 31;
    const int vd = (tid >> 5) * 8;

    const int nkt = 2 * qt + 2;
    for (int kt = 0; kt < nkt; kt++) {
        const int k0 = kt * 64;

        uint4 kr0, kr1, va, vb;
        {
            const __half* kg = g_kh + (((size_t)(b * S_ + k0 + kc)) * H_ + h) * DH + dq;
            kr0 = *(const uint4*)(kg);
            kr1 = *(const uint4*)(kg + 8);
            const __half* vg0 = g_vh + (((size_t)(b * S_ + k0 + 2 * vp)) * H_ + h) * DH + vd;
            const __half* vg1 = vg0 + (size_t)H_ * DH;
            va = *(const uint4*)(vg0);
            vb = *(const uint4*)(vg1);
        }
        __syncthreads();
        {
            const uint32_t* kw = (const uint32_t*)&kr0;
            #pragma unroll
            for (int j = 0; j < 4; j++)
                Ks[(dq / 2 + j) * KSTR2 + kc] = kw[j];
            const uint32_t* kw1 = (const uint32_t*)&kr1;
            #pragma unroll
            for (int j = 0; j < 4; j++)
                Ks[(dq / 2 + 4 + j) * KSTR2 + kc] = kw1[j];
        }
        {
            const __half* ha = (const __half*)&va;
            const __half* hb = (const __half*)&vb;
            uint32_t w[8];
            #pragma unroll
            for (int j = 0; j < 8; j++) {
                __half2 hh = __halves2half2(ha[j], hb[j]);
                w[j] = *(uint32_t*)&hh;
            }
            *(uint4*)&Vs[vp * VSTR2 + vd]     = *(uint4*)&w[0];
            *(uint4*)&Vs[vp * VSTR2 + vd + 4] = *(uint4*)&w[4];
        }
        __syncthreads();

        float s[8][4];
        #pragma unroll
        for (int nt = 0; nt < 8; nt++)
            #pragma unroll
            for (int r = 0; r < 4; r++) s[nt][r] = 0.f;

        #pragma unroll
        for (int ks = 0; ks < 4; ks++) {
            const int kb = ks * 8;
            uint32_t a0 = Qs[(wrow0 + g) * QSTR + kb + t];
            uint32_t a1 = Qs[(wrow0 + g + 8) * QSTR + kb + t];
            uint32_t a2 = Qs[(wrow0 + g) * QSTR + kb + t + 4];
            uint32_t a3 = Qs[(wrow0 + g + 8) * QSTR + kb + t + 4];
            #pragma unroll
            for (int nt = 0; nt < 8; nt++) {
                uint32_t b0 = Ks[(kb + t) * KSTR2 + nt * 8 + g];
                uint32_t b1 = Ks[(kb + t + 4) * KSTR2 + nt * 8 + g];
                MMA_F16(s[nt][0], s[nt][1], s[nt][2], s[nt][3],
                        a0, a1, a2, a3, b0, b1);
            }
        }

        if (kt >= 2 * qt) {
            const int row0 = q0 + wrow0 + g;
            #pragma unroll
            for (int nt = 0; nt < 8; nt++) {
                const int col = k0 + nt * 8 + 2 * t;
                if (col     > row0)     s[nt][0] = -INFINITY;
                if (col + 1 > row0)     s[nt][1] = -INFINITY;
                if (col     > row0 + 8) s[nt][2] = -INFINITY;
                if (col + 1 > row0 + 8) s[nt][3] = -INFINITY;
            }
        }

        float mx0 = -INFINITY, mx1 = -INFINITY;
        #pragma unroll
        for (int nt = 0; nt < 8; nt++) {
            mx0 = fmaxf(mx0, fmaxf(s[nt][0], s[nt][1]));
            mx1 = fmaxf(mx1, fmaxf(s[nt][2], s[nt][3]));
        }
        mx0 = fmaxf(mx0, __shfl_xor_sync(0xffffffffu, mx0, 1));
        mx0 = fmaxf(mx0, __shfl_xor_sync(0xffffffffu, mx0, 2));
        mx1 = fmaxf(mx1, __shfl_xor_sync(0xffffffffu, mx1, 1));
        mx1 = fmaxf(mx1, __shfl_xor_sync(0xffffffffu, mx1, 2));

        const float mn0 = fmaxf(m0r, mx0);
        const float mn1 = fmaxf(m1r, mx1);
        const float sc0 = __expf(m0r - mn0);
        const float sc1 = __expf(m1r - mn1);

        float ls0 = 0.f, ls1 = 0.f;
        #pragma unroll
        for (int nt = 0; nt < 8; nt++) {
            float p0 = __expf(s[nt][0] - mn0);
            float p1 = __expf(s[nt][1] - mn0);
            float p2 = __expf(s[nt][2] - mn1);
            float p3 = __expf(s[nt][3] - mn1);
            ls0 += p0 + p1;
            ls1 += p2 + p3;
            __half2 h01 = __floats2half2_rn(p0, p1);
            __half2 h23 = __floats2half2_rn(p2, p3);
            Ps[g * PSTR2 + nt * 4 + t]       = *(uint32_t*)&h01;
            Ps[(g + 8) * PSTR2 + nt * 4 + t] = *(uint32_t*)&h23;
        }
        ls0 += __shfl_xor_sync(0xffffffffu, ls0, 1);
        ls0 += __shfl_xor_sync(0xffffffffu, ls0, 2);
        ls1 += __shfl_xor_sync(0xffffffffu, ls1, 1);
        ls1 += __shfl_xor_sync(0xffffffffu, ls1, 2);
        l0 = l0 * sc0 + ls0;
        l1 = l1 * sc1 + ls1;
        #pragma unroll
        for (int nt = 0; nt < 8; nt++) {
            o[nt][0] *= sc0; o[nt][1] *= sc0;
            o[nt][2] *= sc1; o[nt][3] *= sc1;
        }
        m0r = mn0; m1r = mn1;

        __syncwarp();

        #pragma unroll
        for (int ks = 0; ks < 4; ks++) {
            const int kb = ks * 8;
            uint32_t a0 = Ps[g * PSTR2 + kb + t];
            uint32_t a1 = Ps[(g + 8) * PSTR2 + kb + t];
            uint32_t a2 = Ps[g * PSTR2 + kb + t + 4];
            uint32_t a3 = Ps[(g + 8) * PSTR2 + kb + t + 4];
            #pragma unroll
            for (int nt = 0; nt < 8; nt++) {
                uint32_t b0 = Vs[(kb + t) * VSTR2 + nt * 8 + g];
                uint32_t b1 = Vs[(kb + t + 4) * VSTR2 + nt * 8 + g];
                MMA_F16(o[nt][0], o[nt][1], o[nt][2], o[nt][3],
                        a0, a1, a2, a3, b0, b1);
            }
        }
        __syncwarp();
    }

    const float i0 = 1.f / l0;
    const float i1 = 1.f / l1;
    __half* xg0 = g_xh + (((size_t)(b * S_ + q0 + wrow0 + g)) * H_ + h) * DH;
    __half* xg1 = xg0 + (size_t)8 * H_ * DH;
    #pragma unroll
    for (int nt = 0; nt < 8; nt++) {
        *(__half2*)(xg0 + nt * 8 + 2 * t) = __floats2half2_rn(o[nt][0] * i0, o[nt][1] * i0);
        *(__half2*)(xg1 + nt * 8 + 2 * t) = __floats2half2_rn(o[nt][2] * i1, o[nt][3] * i1);
    }
}

// ---------------------------------------------------------------------------
extern "C" void kernel_launch(void* const* d_in, const int* in_sizes, int n_in,
                              void* d_out, int out_size)
{
    (void)in_sizes; (void)n_in; (void)out_size;
    const float* inputs = (const float*)d_in[0];
    const float* w_q    = (const float*)d_in[1];
    const float* w_k    = (const float*)d_in[2];
    const float* w_v    = (const float*)d_in[3];
    const float* w_out  = (const float*)d_in[4];
    const int*   segpos = (const int*)d_in[5];
    float* out = (float*)d_out;

    __half *qh, *kh, *vh, *xh, *ah, *wth;
    cudaGetSymbolAddress((void**)&qh, g_qh);
    cudaGetSymbolAddress((void**)&kh, g_kh);
    cudaGetSymbolAddress((void**)&vh, g_vh);
    cudaGetSymbolAddress((void**)&xh, g_xh);
    cudaGetSymbolAddress((void**)&ah, g_ah);
    cudaGetSymbolAddress((void**)&wth, g_wth);

    build_tab<<<S_ * 32 / 256, 256>>>();
    to_half<<<B_ * S_ * D_ / (256 * 8), 256>>>(inputs, ah);
    transpose_half<<<dim3(32, 32, 4), dim3(32, 8)>>>(w_q, w_k, w_v, w_out, wth);

    cudaFuncSetAttribute(gemm_h, cudaFuncAttributeMaxDynamicSharedMemorySize, GSMEM_BYTES);
    // fused QKV with rope epilogue: N = 3072
    gemm_h<<<dim3(24, 64), 256, GSMEM_BYTES>>>(ah, wth, nullptr, qh, kh, vh, segpos, 1);

    const int fsmem = FH_SMEM_WORDS * (int)sizeof(uint32_t);
    cudaFuncSetAttribute(flash_h, cudaFuncAttributeMaxDynamicSharedMemorySize, fsmem);
    flash_h<<<dim3(S_ / BQ, H_, B_), 256, fsmem>>>();

    // out-projection: plain fp32
    gemm_h<<<dim3(8, 64), 256, GSMEM_BYTES>>>(xh, wth + (size_t)3 * 1024 * 1024,
                                              out, nullptr, nullptr, nullptr, nullptr, 0);
}